// round 7
// baseline (speedup 1.0000x reference)
#include <cuda_runtime.h>
#include <cuda_fp16.h>
#include <cstdint>

#define NN 50000
#define EE 800000
#define FF 512
#define HH 128
#define CC 40
#define NCAT 640     // (1 + 4) * 128
#define NB_SCAN 196  // ceil(NN / 256)
#define WMAIN (FF * HH + 10 * HH * HH)   // 229376 (W_in + 10x W_gcn)
#define WOUTN (NCAT * CC)                // 25600

// ---------------- scratch (device globals; no allocation allowed) -----------
static __device__ __align__(256) float    g_deg[NN];
// per-chain fp16 GEMM outputs (messages)
static __device__ __align__(256) __half2  g_hwh0[NN * 64];
static __device__ __align__(256) __half2  g_hwh1[NN * 64];
static __device__ __align__(256) __half2  g_hwh2[NN * 64];
static __device__ __align__(256) __half2  g_hwh3[NN * 64];
// per-chain fp32 temporaries
static __device__ __align__(256) float    g_c2a[NN * HH];
static __device__ __align__(256) float    g_c3a[NN * HH];
static __device__ __align__(256) float    g_c3b[NN * HH];
static __device__ __align__(256) float    g_c4a[NN * HH];
static __device__ __align__(256) float    g_c4b[NN * HH];
static __device__ __align__(256) float    g_cat[(size_t)NN * NCAT];
// pre-split weights (tf32 hi/lo)
static __device__ __align__(256) uint32_t g_bh[WMAIN], g_bl[WMAIN];
static __device__ __align__(256) uint32_t g_woh[WOUTN], g_wol[WOUTN];
// CSR scratch
static __device__ __align__(256) int   g_cnt[NN];
static __device__ __align__(256) int   g_rowptr[NN + 1];
static __device__ __align__(256) int   g_cursor[NN];
static __device__ __align__(256) int   g_csrc[EE];
static __device__ __align__(256) float g_cw[EE];
static __device__ __align__(256) int   g_bsum[256];
static __device__ __align__(256) int   g_boff[256];

__device__ __forceinline__ uint32_t f2tf32(float x) {
    uint32_t r;
    asm("cvt.rna.tf32.f32 %0, %1;" : "=r"(r) : "f"(x));
    return r;
}

// ---------------- weight pre-split ------------------------------------------
__global__ void k_wsplit(const float* __restrict__ W_in,
                         const float* __restrict__ W_gcn,
                         const float* __restrict__ W_out,
                         uint32_t* __restrict__ bh, uint32_t* __restrict__ bl,
                         uint32_t* __restrict__ woh, uint32_t* __restrict__ wol) {
    int i = blockIdx.x * blockDim.x + threadIdx.x;
    if (i < WMAIN) {
        float v = (i < FF * HH) ? W_in[i] : W_gcn[i - FF * HH];
        uint32_t h = f2tf32(v);
        bh[i] = h;
        bl[i] = f2tf32(v - __uint_as_float(h));
    } else if (i < WMAIN + WOUTN) {
        int j = i - WMAIN;
        float v = W_out[j];
        uint32_t h = f2tf32(v);
        woh[j] = h;
        wol[j] = f2tf32(v - __uint_as_float(h));
    }
}

// ---------------- degree / CSR build ----------------------------------------
__global__ void k_deg_init(float* __restrict__ deg, int* __restrict__ cnt) {
    int i = blockIdx.x * blockDim.x + threadIdx.x;
    if (i < NN) { deg[i] = 1.0f; cnt[i] = 0; }
}

__global__ void k_deg_acc(const int* __restrict__ ei, const float* __restrict__ ew,
                          float* __restrict__ deg, int* __restrict__ cnt) {
    int e = blockIdx.x * blockDim.x + threadIdx.x;
    if (e < EE) {
        int d = ei[EE + e];
        atomicAdd(&deg[d], ew[e]);
        atomicAdd(&cnt[d], 1);
    }
}

__global__ void k_scan1(const int* __restrict__ cnt, int* __restrict__ bsum) {
    __shared__ int s[256];
    int i = blockIdx.x * 256 + threadIdx.x;
    s[threadIdx.x] = (i < NN) ? cnt[i] : 0;
    __syncthreads();
    for (int off = 128; off > 0; off >>= 1) {
        if (threadIdx.x < off) s[threadIdx.x] += s[threadIdx.x + off];
        __syncthreads();
    }
    if (threadIdx.x == 0) bsum[blockIdx.x] = s[0];
}

__global__ void k_scan2(const int* __restrict__ bsum, int* __restrict__ boff,
                        int* __restrict__ rowptr) {
    __shared__ int s[256];
    int t = threadIdx.x;
    int v = (t < NB_SCAN) ? bsum[t] : 0;
    s[t] = v;
    __syncthreads();
    for (int off = 1; off < 256; off <<= 1) {
        int u = (t >= off) ? s[t - off] : 0;
        __syncthreads();
        s[t] += u;
        __syncthreads();
    }
    boff[t] = s[t] - v;
    if (t == 255) rowptr[NN] = s[255];
}

__global__ void k_scan3(const int* __restrict__ cnt, const int* __restrict__ boff,
                        int* __restrict__ rowptr, int* __restrict__ cursor) {
    __shared__ int s[256];
    int i = blockIdx.x * 256 + threadIdx.x;
    int t = threadIdx.x;
    int v = (i < NN) ? cnt[i] : 0;
    s[t] = v;
    __syncthreads();
    for (int off = 1; off < 256; off <<= 1) {
        int u = (t >= off) ? s[t - off] : 0;
        __syncthreads();
        s[t] += u;
        __syncthreads();
    }
    int ex = boff[blockIdx.x] + s[t] - v;
    if (i < NN) { rowptr[i] = ex; cursor[i] = ex; }
}

__global__ void k_fill(const int* __restrict__ ei, const float* __restrict__ ew,
                       const float* __restrict__ deg, int* __restrict__ cursor,
                       int* __restrict__ csrc, float* __restrict__ cw) {
    int e = blockIdx.x * blockDim.x + threadIdx.x;
    if (e < EE) {
        int s = ei[e], d = ei[EE + e];
        int pos = atomicAdd(&cursor[d], 1);
        csrc[pos] = s;
        cw[pos]   = ew[e] * rsqrtf(deg[s]) * rsqrtf(deg[d]);
    }
}

// ---------------- 3xTF32 tensor-core GEMM -----------------------------------
__device__ __forceinline__ void mma_tf32(float c[4], const uint32_t a[4],
                                         uint32_t b0, uint32_t b1) {
    asm volatile(
        "mma.sync.aligned.m16n8k8.row.col.f32.tf32.tf32.f32 "
        "{%0,%1,%2,%3}, {%4,%5,%6,%7}, {%8,%9}, {%0,%1,%2,%3};"
        : "+f"(c[0]), "+f"(c[1]), "+f"(c[2]), "+f"(c[3])
        : "r"(a[0]), "r"(a[1]), "r"(a[2]), "r"(a[3]), "r"(b0), "r"(b1));
}

#define BK 16
#define LDP 136   // 136 mod 32 == 8 -> conflict-free fragment loads

__global__ __launch_bounds__(256) void k_mma(
    const float* __restrict__ A, int lda,
    const uint32_t* __restrict__ Bh_g, const uint32_t* __restrict__ Bl_g,
    const float* __restrict__ bias, float* __restrict__ C, int ldc,
    __half2* __restrict__ hout, int M, int K)
{
    __shared__ uint32_t Ah[BK * LDP], Al[BK * LDP];
    __shared__ uint32_t Bh[BK * LDP], Bl[BK * LDP];

    const int tid  = threadIdx.x;
    const int wid  = tid >> 5;
    const int lane = tid & 31;
    const int g    = lane >> 2;
    const int tg   = lane & 3;
    const int wm   = (wid & 3) * 32;
    const int wn   = (wid >> 2) * 64;
    const int brow = blockIdx.x * 128;

    int ar[2], ac[2], br[2], bc[2];
#pragma unroll
    for (int l = 0; l < 2; l++) {
        int v = tid + l * 256;
        ar[l] = v >> 2;  ac[l] = (v & 3) * 4;
        br[l] = v >> 5;  bc[l] = (v & 31) * 4;
    }

    float acc[2][8][4];
#pragma unroll
    for (int mt = 0; mt < 2; mt++)
#pragma unroll
        for (int nt = 0; nt < 8; nt++)
#pragma unroll
            for (int j = 0; j < 4; j++) acc[mt][nt][j] = 0.0f;

    const int nt_tiles = K / BK;

    float4 pa[2];
    uint4  pbh[2], pbl[2];

    auto fetch = [&](int t) {
#pragma unroll
        for (int l = 0; l < 2; l++) {
            int grow = brow + ar[l];
            pa[l] = make_float4(0.f, 0.f, 0.f, 0.f);
            if (grow < M)
                pa[l] = *(const float4*)&A[(size_t)grow * lda + t * BK + ac[l]];
            pbh[l] = *(const uint4*)&Bh_g[(size_t)(t * BK + br[l]) * 128 + bc[l]];
            pbl[l] = *(const uint4*)&Bl_g[(size_t)(t * BK + br[l]) * 128 + bc[l]];
        }
    };
    auto store = [&]() {
#pragma unroll
        for (int l = 0; l < 2; l++) {
            float aa[4] = {pa[l].x, pa[l].y, pa[l].z, pa[l].w};
#pragma unroll
            for (int j = 0; j < 4; j++) {
                uint32_t hb = f2tf32(aa[j]);
                Ah[(ac[l] + j) * LDP + ar[l]] = hb;
                Al[(ac[l] + j) * LDP + ar[l]] = f2tf32(aa[j] - __uint_as_float(hb));
            }
            *(uint4*)&Bh[br[l] * LDP + bc[l]] = pbh[l];
            *(uint4*)&Bl[br[l] * LDP + bc[l]] = pbl[l];
        }
    };

    fetch(0);
    store();
    __syncthreads();

    for (int t = 0; t < nt_tiles; t++) {
        if (t + 1 < nt_tiles) fetch(t + 1);

#pragma unroll
        for (int ks = 0; ks < 2; ks++) {
            int k0 = ks * 8;
            uint32_t ahf[2][4], alf[2][4];
#pragma unroll
            for (int mt = 0; mt < 2; mt++) {
                int m0 = wm + mt * 16;
                ahf[mt][0] = Ah[(k0 + tg) * LDP + m0 + g];
                ahf[mt][1] = Ah[(k0 + tg) * LDP + m0 + g + 8];
                ahf[mt][2] = Ah[(k0 + tg + 4) * LDP + m0 + g];
                ahf[mt][3] = Ah[(k0 + tg + 4) * LDP + m0 + g + 8];
                alf[mt][0] = Al[(k0 + tg) * LDP + m0 + g];
                alf[mt][1] = Al[(k0 + tg) * LDP + m0 + g + 8];
                alf[mt][2] = Al[(k0 + tg + 4) * LDP + m0 + g];
                alf[mt][3] = Al[(k0 + tg + 4) * LDP + m0 + g + 8];
            }
#pragma unroll
            for (int nt = 0; nt < 8; nt++) {
                int n0 = wn + nt * 8;
                uint32_t b0h = Bh[(k0 + tg) * LDP + n0 + g];
                uint32_t b1h = Bh[(k0 + tg + 4) * LDP + n0 + g];
                uint32_t b0l = Bl[(k0 + tg) * LDP + n0 + g];
                uint32_t b1l = Bl[(k0 + tg + 4) * LDP + n0 + g];
#pragma unroll
                for (int mt = 0; mt < 2; mt++) {
                    mma_tf32(acc[mt][nt], ahf[mt], b0h, b1h);
                    mma_tf32(acc[mt][nt], alf[mt], b0h, b1h);
                    mma_tf32(acc[mt][nt], ahf[mt], b0l, b1l);
                }
            }
        }
        if (t + 1 < nt_tiles) {
            __syncthreads();
            store();
            __syncthreads();
        }
    }

#pragma unroll
    for (int mt = 0; mt < 2; mt++) {
        int r0 = brow + wm + mt * 16 + g;
        int r1 = r0 + 8;
#pragma unroll
        for (int nt = 0; nt < 8; nt++) {
            int col = wn + nt * 8 + tg * 2;
            if (hout) {
                if (r0 < M)
                    hout[(size_t)r0 * 64 + (col >> 1)] =
                        __floats2half2_rn(acc[mt][nt][0], acc[mt][nt][1]);
                if (r1 < M)
                    hout[(size_t)r1 * 64 + (col >> 1)] =
                        __floats2half2_rn(acc[mt][nt][2], acc[mt][nt][3]);
            } else {
                float2 v0 = make_float2(acc[mt][nt][0], acc[mt][nt][1]);
                float2 v1 = make_float2(acc[mt][nt][2], acc[mt][nt][3]);
                if (bias) {
                    float b0 = bias[col], b1 = bias[col + 1];
                    v0.x += b0; v0.y += b1;
                    v1.x += b0; v1.y += b1;
                }
                if (r0 < M) *(float2*)&C[(size_t)r0 * ldc + col] = v0;
                if (r1 < M) *(float2*)&C[(size_t)r1 * ldc + col] = v1;
            }
        }
    }
}

// ---------------- CSR aggregation (fp16 sources, fp32 accum) ----------------
__global__ __launch_bounds__(256) void k_aggr(
    const int* __restrict__ rowptr, const int* __restrict__ csrc,
    const float* __restrict__ cw, const __half2* __restrict__ hwh,
    const float* __restrict__ deg, const float* __restrict__ bias,
    float4* __restrict__ out, int ldo4)
{
    int node = (blockIdx.x * blockDim.x + threadIdx.x) >> 5;
    if (node >= NN) return;
    int lane = threadIdx.x & 31;

    const uint2* mh = (const uint2*)hwh;

    auto loadf4 = [&](int n) -> float4 {
        uint2 p = __ldg(&mh[(size_t)n * 32 + lane]);
        __half2 h0 = *(__half2*)&p.x;
        __half2 h1 = *(__half2*)&p.y;
        float2 f0 = __half22float2(h0);
        float2 f1 = __half22float2(h1);
        return make_float4(f0.x, f0.y, f1.x, f1.y);
    };

    float sn = 1.0f / deg[node];
    float4 self = loadf4(node);
    float4 bb = ((const float4*)bias)[lane];
    float4 acc;
    acc.x = self.x * sn + bb.x;
    acc.y = self.y * sn + bb.y;
    acc.z = self.z * sn + bb.z;
    acc.w = self.w * sn + bb.w;

    int e  = rowptr[node];
    int e1 = rowptr[node + 1];
    for (; e + 3 < e1; e += 4) {
        int   s0 = __ldg(&csrc[e]),     s1 = __ldg(&csrc[e + 1]);
        int   s2 = __ldg(&csrc[e + 2]), s3 = __ldg(&csrc[e + 3]);
        float w0 = __ldg(&cw[e]),       w1 = __ldg(&cw[e + 1]);
        float w2 = __ldg(&cw[e + 2]),   w3 = __ldg(&cw[e + 3]);
        float4 v0 = loadf4(s0), v1 = loadf4(s1), v2 = loadf4(s2), v3 = loadf4(s3);
        acc.x += w0 * v0.x + w1 * v1.x + w2 * v2.x + w3 * v3.x;
        acc.y += w0 * v0.y + w1 * v1.y + w2 * v2.y + w3 * v3.y;
        acc.z += w0 * v0.z + w1 * v1.z + w2 * v2.z + w3 * v3.z;
        acc.w += w0 * v0.w + w1 * v1.w + w2 * v2.w + w3 * v3.w;
    }
    for (; e < e1; e++) {
        int   s0 = __ldg(&csrc[e]);
        float w0 = __ldg(&cw[e]);
        float4 v0 = loadf4(s0);
        acc.x += w0 * v0.x;
        acc.y += w0 * v0.y;
        acc.z += w0 * v0.z;
        acc.w += w0 * v0.w;
    }
    out[(size_t)node * ldo4 + lane] = acc;
}

// ---------------- final: out = cat @ W_out + b_out (3xTF32) -----------------
#define LDO 264   // 264 mod 32 == 8

__global__ __launch_bounds__(256) void k_out(
    const float* __restrict__ cat,
    const uint32_t* __restrict__ Woh, const uint32_t* __restrict__ Wol,
    const float* __restrict__ b, float* __restrict__ out)
{
    __shared__ uint32_t Ah[BK * LDO], Al[BK * LDO];
    __shared__ uint32_t Bh[BK * 40], Bl[BK * 40];

    const int tid  = threadIdx.x;
    const int wid  = tid >> 5;
    const int lane = tid & 31;
    const int g    = lane >> 2;
    const int tg   = lane & 3;
    const int wm   = wid * 32;
    const int brow = blockIdx.x * 256;

    float acc[2][5][4];
#pragma unroll
    for (int mt = 0; mt < 2; mt++)
#pragma unroll
        for (int nt = 0; nt < 5; nt++)
#pragma unroll
            for (int j = 0; j < 4; j++) acc[mt][nt][j] = 0.0f;

    for (int kc = 0; kc < NCAT; kc += BK) {
#pragma unroll
        for (int l = 0; l < 4; l++) {
            int v  = tid + l * 256;
            int r  = v >> 2;
            int c4 = (v & 3) * 4;
            int grow = brow + r;
            float4 av = make_float4(0.f, 0.f, 0.f, 0.f);
            if (grow < NN) av = *(const float4*)&cat[(size_t)grow * NCAT + kc + c4];
            float aa[4] = {av.x, av.y, av.z, av.w};
#pragma unroll
            for (int j = 0; j < 4; j++) {
                uint32_t hb = f2tf32(aa[j]);
                Ah[(c4 + j) * LDO + r] = hb;
                Al[(c4 + j) * LDO + r] = f2tf32(aa[j] - __uint_as_float(hb));
            }
        }
        for (int idx = tid; idx < BK * 40; idx += 256) {
            Bh[idx] = Woh[kc * 40 + idx];
            Bl[idx] = Wol[kc * 40 + idx];
        }
        __syncthreads();

#pragma unroll
        for (int ks = 0; ks < 2; ks++) {
            int k0 = ks * 8;
            uint32_t ahf[2][4], alf[2][4];
#pragma unroll
            for (int mt = 0; mt < 2; mt++) {
                int m0 = wm + mt * 16;
                ahf[mt][0] = Ah[(k0 + tg) * LDO + m0 + g];
                ahf[mt][1] = Ah[(k0 + tg) * LDO + m0 + g + 8];
                ahf[mt][2] = Ah[(k0 + tg + 4) * LDO + m0 + g];
                ahf[mt][3] = Ah[(k0 + tg + 4) * LDO + m0 + g + 8];
                alf[mt][0] = Al[(k0 + tg) * LDO + m0 + g];
                alf[mt][1] = Al[(k0 + tg) * LDO + m0 + g + 8];
                alf[mt][2] = Al[(k0 + tg + 4) * LDO + m0 + g];
                alf[mt][3] = Al[(k0 + tg + 4) * LDO + m0 + g + 8];
            }
#pragma unroll
            for (int nt = 0; nt < 5; nt++) {
                int n0 = nt * 8;
                uint32_t b0h = Bh[(k0 + tg) * 40 + n0 + g];
                uint32_t b1h = Bh[(k0 + tg + 4) * 40 + n0 + g];
                uint32_t b0l = Bl[(k0 + tg) * 40 + n0 + g];
                uint32_t b1l = Bl[(k0 + tg + 4) * 40 + n0 + g];
#pragma unroll
                for (int mt = 0; mt < 2; mt++) {
                    mma_tf32(acc[mt][nt], ahf[mt], b0h, b1h);
                    mma_tf32(acc[mt][nt], alf[mt], b0h, b1h);
                    mma_tf32(acc[mt][nt], ahf[mt], b0l, b1l);
                }
            }
        }
        __syncthreads();
    }

#pragma unroll
    for (int mt = 0; mt < 2; mt++) {
        int r0 = brow + wm + mt * 16 + g;
        int r1 = r0 + 8;
#pragma unroll
        for (int nt = 0; nt < 5; nt++) {
            int col = nt * 8 + tg * 2;
            float b0 = b[col], b1 = b[col + 1];
            if (r0 < NN) {
                float2 v = make_float2(acc[mt][nt][0] + b0, acc[mt][nt][1] + b1);
                *(float2*)&out[(size_t)r0 * CC + col] = v;
            }
            if (r1 < NN) {
                float2 v = make_float2(acc[mt][nt][2] + b0, acc[mt][nt][3] + b1);
                *(float2*)&out[(size_t)r1 * CC + col] = v;
            }
        }
    }
}

// ---------------- streams / events (created once, before harness checkpoints)
struct GraphCtx {
    cudaStream_t s_csr, s_ch[4];
    cudaEvent_t  e_root, e_h, e_csr, e_done[4];
    GraphCtx() {
        cudaFree(0);   // init runtime early
        cudaStreamCreateWithFlags(&s_csr, cudaStreamNonBlocking);
        for (int i = 0; i < 4; i++)
            cudaStreamCreateWithFlags(&s_ch[i], cudaStreamNonBlocking);
        cudaEventCreateWithFlags(&e_root, cudaEventDisableTiming);
        cudaEventCreateWithFlags(&e_h,    cudaEventDisableTiming);
        cudaEventCreateWithFlags(&e_csr,  cudaEventDisableTiming);
        for (int i = 0; i < 4; i++)
            cudaEventCreateWithFlags(&e_done[i], cudaEventDisableTiming);
    }
};
static GraphCtx g_ctx;

// ---------------- launch -----------------------------------------------------
extern "C" void kernel_launch(void* const* d_in, const int* in_sizes, int n_in,
                              void* d_out, int out_size) {
    const float* x     = (const float*)d_in[0];
    const int*   ei    = (const int*)  d_in[1];
    const float* ew    = (const float*)d_in[2];
    const float* W_in  = (const float*)d_in[3];
    const float* b_in  = (const float*)d_in[4];
    const float* W_gcn = (const float*)d_in[5];
    const float* b_gcn = (const float*)d_in[6];
    const float* W_out = (const float*)d_in[7];
    const float* b_out = (const float*)d_in[8];
    float* out = (float*)d_out;

    float *deg, *cat, *cw;
    float *c2a, *c3a, *c3b, *c4a, *c4b;
    __half2* hwh[4];
    uint32_t *bh, *bl, *woh, *wol;
    int *cnt, *rowptr, *cursor, *csrc, *bsum, *boff;
    cudaGetSymbolAddress((void**)&deg,     g_deg);
    cudaGetSymbolAddress((void**)&hwh[0],  g_hwh0);
    cudaGetSymbolAddress((void**)&hwh[1],  g_hwh1);
    cudaGetSymbolAddress((void**)&hwh[2],  g_hwh2);
    cudaGetSymbolAddress((void**)&hwh[3],  g_hwh3);
    cudaGetSymbolAddress((void**)&c2a,     g_c2a);
    cudaGetSymbolAddress((void**)&c3a,     g_c3a);
    cudaGetSymbolAddress((void**)&c3b,     g_c3b);
    cudaGetSymbolAddress((void**)&c4a,     g_c4a);
    cudaGetSymbolAddress((void**)&c4b,     g_c4b);
    cudaGetSymbolAddress((void**)&cat,     g_cat);
    cudaGetSymbolAddress((void**)&bh,      g_bh);
    cudaGetSymbolAddress((void**)&bl,      g_bl);
    cudaGetSymbolAddress((void**)&woh,     g_woh);
    cudaGetSymbolAddress((void**)&wol,     g_wol);
    cudaGetSymbolAddress((void**)&cnt,     g_cnt);
    cudaGetSymbolAddress((void**)&rowptr,  g_rowptr);
    cudaGetSymbolAddress((void**)&cursor,  g_cursor);
    cudaGetSymbolAddress((void**)&csrc,    g_csrc);
    cudaGetSymbolAddress((void**)&cw,      g_cw);
    cudaGetSymbolAddress((void**)&bsum,    g_bsum);
    cudaGetSymbolAddress((void**)&boff,    g_boff);

    cudaStream_t sM = 0;                 // harness capture-origin stream
    cudaStream_t sC = g_ctx.s_csr;
    cudaStream_t* sc = g_ctx.s_ch;

    // fork
    cudaEventRecord(g_ctx.e_root, sM);
    cudaStreamWaitEvent(sC, g_ctx.e_root, 0);
    cudaStreamWaitEvent(sc[0], g_ctx.e_root, 0);

    // --- CSR build on sC (parallel with weight split + input GEMM) ---
    k_deg_init<<<(NN + 255) / 256, 256, 0, sC>>>(deg, cnt);
    k_deg_acc <<<(EE + 255) / 256, 256, 0, sC>>>(ei, ew, deg, cnt);
    k_scan1   <<<NB_SCAN, 256, 0, sC>>>(cnt, bsum);
    k_scan2   <<<1, 256, 0, sC>>>(bsum, boff, rowptr);
    k_scan3   <<<NB_SCAN, 256, 0, sC>>>(cnt, boff, rowptr, cursor);
    k_fill    <<<(EE + 255) / 256, 256, 0, sC>>>(ei, ew, deg, cursor, csrc, cw);
    cudaEventRecord(g_ctx.e_csr, sC);

    const int gb = (NN + 127) / 128;

    // --- weight split + input GEMM on sc[0]; h -> cat[:, 0:128] ---
    k_wsplit<<<(WMAIN + WOUTN + 255) / 256, 256, 0, sc[0]>>>(
        W_in, W_gcn, W_out, bh, bl, woh, wol);
    k_mma<<<gb, 256, 0, sc[0]>>>(x, FF, bh, bl, b_in, cat, NCAT, nullptr, NN, FF);
    cudaEventRecord(g_ctx.e_h, sc[0]);

    // chains 1..3 wait for h (chain 0 already in-order on sc[0])
    for (int c = 1; c < 4; c++)
        cudaStreamWaitEvent(sc[c], g_ctx.e_h, 0);

    const float* h = cat;               // stride NCAT

    // one GCN conv on stream s: hwh_c = fp16(in @ Wk); dst = aggr(...)
    auto gcn = [&](cudaStream_t s, __half2* hw_c, const float* in, int lda,
                   int k, float* dst, int ldo, bool wait_csr) {
        k_mma <<<gb, 256, 0, s>>>(in, lda, bh + FF * HH + (size_t)k * HH * HH,
                                  bl + FF * HH + (size_t)k * HH * HH,
                                  nullptr, nullptr, 0, hw_c, NN, HH);
        if (wait_csr) cudaStreamWaitEvent(s, g_ctx.e_csr, 0);
        k_aggr<<<(NN * 32 + 255) / 256, 256, 0, s>>>(rowptr, csrc, cw, hw_c, deg,
                                                     b_gcn + (size_t)k * HH,
                                                     (float4*)dst, ldo / 4);
    };

    // chain 1 (1 conv) on sc[0]
    gcn(sc[0], hwh[0], h, NCAT, 0, cat + 1 * HH, NCAT, true);
    cudaEventRecord(g_ctx.e_done[0], sc[0]);

    // chain 2 (2 convs) on sc[1]
    gcn(sc[1], hwh[1], h,   NCAT, 1, c2a, HH, true);
    gcn(sc[1], hwh[1], c2a, HH,   2, cat + 2 * HH, NCAT, false);
    cudaEventRecord(g_ctx.e_done[1], sc[1]);

    // chain 3 (3 convs) on sc[2]
    gcn(sc[2], hwh[2], h,   NCAT, 3, c3a, HH, true);
    gcn(sc[2], hwh[2], c3a, HH,   4, c3b, HH, false);
    gcn(sc[2], hwh[2], c3b, HH,   5, cat + 3 * HH, NCAT, false);
    cudaEventRecord(g_ctx.e_done[2], sc[2]);

    // chain 4 (4 convs) on sc[3]
    gcn(sc[3], hwh[3], h,   NCAT, 6, c4a, HH, true);
    gcn(sc[3], hwh[3], c4a, HH,   7, c4b, HH, false);
    gcn(sc[3], hwh[3], c4b, HH,   8, c4a, HH, false);
    gcn(sc[3], hwh[3], c4a, HH,   9, cat + 4 * HH, NCAT, false);
    cudaEventRecord(g_ctx.e_done[3], sc[3]);

    // join + final GEMM on capture-origin stream
    for (int c = 0; c < 4; c++)
        cudaStreamWaitEvent(sM, g_ctx.e_done[c], 0);
    k_out<<<(NN + 255) / 256, 256, 0, sM>>>(cat, woh, wol, b_out, out);
}

// round 8
// speedup vs baseline: 1.5452x; 1.5452x over previous
#include <cuda_runtime.h>
#include <cuda_fp16.h>
#include <cstdint>

#define NN 50000
#define EE 800000
#define FF 512
#define HH 128
#define CC 40
#define NCAT 640     // (1 + 4) * 128
#define NB_SCAN 196  // ceil(NN / 256)
#define WMAIN (FF * HH + 10 * HH * HH)   // 229376 (W_in + 10x W_gcn)
#define WOUTN (NCAT * CC)                // 25600

// ---------------- scratch (device globals; no allocation allowed) -----------
static __device__ __align__(256) float    g_deg[NN];
static __device__ __align__(256) __half2  g_hwh[NN * 64];      // fp16 messages
static __device__ __align__(256) __half   g_t0[NN * HH];       // fp16 chain temps
static __device__ __align__(256) __half   g_t1[NN * HH];
static __device__ __align__(256) __half   g_cat[(size_t)NN * NCAT];  // fp16 concat
// pre-split weights (tf32 hi/lo)
static __device__ __align__(256) uint32_t g_bh[WMAIN], g_bl[WMAIN];
static __device__ __align__(256) uint32_t g_woh[WOUTN], g_wol[WOUTN];
// CSR scratch
static __device__ __align__(256) int   g_cnt[NN];
static __device__ __align__(256) int   g_rowptr[NN + 1];
static __device__ __align__(256) int   g_cursor[NN];
static __device__ __align__(256) int   g_csrc[EE];
static __device__ __align__(256) float g_cw[EE];
static __device__ __align__(256) int   g_bsum[256];
static __device__ __align__(256) int   g_boff[256];

__device__ __forceinline__ uint32_t f2tf32(float x) {
    uint32_t r;
    asm("cvt.rna.tf32.f32 %0, %1;" : "=r"(r) : "f"(x));
    return r;
}

__device__ __forceinline__ void mma_tf32(float c[4], const uint32_t a[4],
                                         uint32_t b0, uint32_t b1) {
    asm volatile(
        "mma.sync.aligned.m16n8k8.row.col.f32.tf32.tf32.f32 "
        "{%0,%1,%2,%3}, {%4,%5,%6,%7}, {%8,%9}, {%0,%1,%2,%3};"
        : "+f"(c[0]), "+f"(c[1]), "+f"(c[2]), "+f"(c[3])
        : "r"(a[0]), "r"(a[1]), "r"(a[2]), "r"(a[3]), "r"(b0), "r"(b1));
}

// ---------------- weight pre-split ------------------------------------------
__global__ void k_wsplit(const float* __restrict__ W_in,
                         const float* __restrict__ W_gcn,
                         const float* __restrict__ W_out,
                         uint32_t* __restrict__ bh, uint32_t* __restrict__ bl,
                         uint32_t* __restrict__ woh, uint32_t* __restrict__ wol) {
    int i = blockIdx.x * blockDim.x + threadIdx.x;
    if (i < WMAIN) {
        float v = (i < FF * HH) ? W_in[i] : W_gcn[i - FF * HH];
        uint32_t h = f2tf32(v);
        bh[i] = h;
        bl[i] = f2tf32(v - __uint_as_float(h));
    } else if (i < WMAIN + WOUTN) {
        int j = i - WMAIN;
        float v = W_out[j];
        uint32_t h = f2tf32(v);
        woh[j] = h;
        wol[j] = f2tf32(v - __uint_as_float(h));
    }
}

// ---------------- degree / CSR build ----------------------------------------
__global__ void k_deg_init(float* __restrict__ deg, int* __restrict__ cnt) {
    int i = blockIdx.x * blockDim.x + threadIdx.x;
    if (i < NN) { deg[i] = 1.0f; cnt[i] = 0; }
}

__global__ void k_deg_acc(const int* __restrict__ ei, const float* __restrict__ ew,
                          float* __restrict__ deg, int* __restrict__ cnt) {
    int e = blockIdx.x * blockDim.x + threadIdx.x;
    if (e < EE) {
        int d = ei[EE + e];
        atomicAdd(&deg[d], ew[e]);
        atomicAdd(&cnt[d], 1);
    }
}

__global__ void k_scan1(const int* __restrict__ cnt, int* __restrict__ bsum) {
    __shared__ int s[256];
    int i = blockIdx.x * 256 + threadIdx.x;
    s[threadIdx.x] = (i < NN) ? cnt[i] : 0;
    __syncthreads();
    for (int off = 128; off > 0; off >>= 1) {
        if (threadIdx.x < off) s[threadIdx.x] += s[threadIdx.x + off];
        __syncthreads();
    }
    if (threadIdx.x == 0) bsum[blockIdx.x] = s[0];
}

__global__ void k_scan2(const int* __restrict__ bsum, int* __restrict__ boff,
                        int* __restrict__ rowptr) {
    __shared__ int s[256];
    int t = threadIdx.x;
    int v = (t < NB_SCAN) ? bsum[t] : 0;
    s[t] = v;
    __syncthreads();
    for (int off = 1; off < 256; off <<= 1) {
        int u = (t >= off) ? s[t - off] : 0;
        __syncthreads();
        s[t] += u;
        __syncthreads();
    }
    boff[t] = s[t] - v;
    if (t == 255) rowptr[NN] = s[255];
}

__global__ void k_scan3(const int* __restrict__ cnt, const int* __restrict__ boff,
                        int* __restrict__ rowptr, int* __restrict__ cursor) {
    __shared__ int s[256];
    int i = blockIdx.x * 256 + threadIdx.x;
    int t = threadIdx.x;
    int v = (i < NN) ? cnt[i] : 0;
    s[t] = v;
    __syncthreads();
    for (int off = 1; off < 256; off <<= 1) {
        int u = (t >= off) ? s[t - off] : 0;
        __syncthreads();
        s[t] += u;
        __syncthreads();
    }
    int ex = boff[blockIdx.x] + s[t] - v;
    if (i < NN) { rowptr[i] = ex; cursor[i] = ex; }
}

__global__ void k_fill(const int* __restrict__ ei, const float* __restrict__ ew,
                       const float* __restrict__ deg, int* __restrict__ cursor,
                       int* __restrict__ csrc, float* __restrict__ cw) {
    int e = blockIdx.x * blockDim.x + threadIdx.x;
    if (e < EE) {
        int s = ei[e], d = ei[EE + e];
        int pos = atomicAdd(&cursor[d], 1);
        csrc[pos] = s;
        cw[pos]   = ew[e] * rsqrtf(deg[s]) * rsqrtf(deg[d]);
    }
}

#define BK 16
#define LDP 136   // 136 mod 32 == 8 -> conflict-free fragment loads

// ---------------- input GEMM: fp32 A, 3xTF32, fp16 out into cat -------------
// C16[M,128] = A[M,512] @ B + bias ; block 128x128, 8 warps 4x2.
__global__ __launch_bounds__(256) void k_mma_in(
    const float* __restrict__ A,
    const uint32_t* __restrict__ Bh_g, const uint32_t* __restrict__ Bl_g,
    const float* __restrict__ bias, __half* __restrict__ catH)
{
    __shared__ uint32_t Ah[BK * LDP], Al[BK * LDP];
    __shared__ uint32_t Bh[BK * LDP], Bl[BK * LDP];

    const int tid  = threadIdx.x;
    const int wid  = tid >> 5;
    const int lane = tid & 31;
    const int g    = lane >> 2;
    const int tg   = lane & 3;
    const int wm   = (wid & 3) * 32;
    const int wn   = (wid >> 2) * 64;
    const int brow = blockIdx.x * 128;

    int ar[2], ac[2], br[2], bc[2];
#pragma unroll
    for (int l = 0; l < 2; l++) {
        int v = tid + l * 256;
        ar[l] = v >> 2;  ac[l] = (v & 3) * 4;
        br[l] = v >> 5;  bc[l] = (v & 31) * 4;
    }

    float acc[2][8][4];
#pragma unroll
    for (int mt = 0; mt < 2; mt++)
#pragma unroll
        for (int nt = 0; nt < 8; nt++)
#pragma unroll
            for (int j = 0; j < 4; j++) acc[mt][nt][j] = 0.0f;

    const int nt_tiles = FF / BK;

    float4 pa[2];
    uint4  pbh[2], pbl[2];

    auto fetch = [&](int t) {
#pragma unroll
        for (int l = 0; l < 2; l++) {
            int grow = brow + ar[l];
            pa[l] = make_float4(0.f, 0.f, 0.f, 0.f);
            if (grow < NN)
                pa[l] = *(const float4*)&A[(size_t)grow * FF + t * BK + ac[l]];
            pbh[l] = *(const uint4*)&Bh_g[(size_t)(t * BK + br[l]) * 128 + bc[l]];
            pbl[l] = *(const uint4*)&Bl_g[(size_t)(t * BK + br[l]) * 128 + bc[l]];
        }
    };
    auto store = [&]() {
#pragma unroll
        for (int l = 0; l < 2; l++) {
            float aa[4] = {pa[l].x, pa[l].y, pa[l].z, pa[l].w};
#pragma unroll
            for (int j = 0; j < 4; j++) {
                uint32_t hb = f2tf32(aa[j]);
                Ah[(ac[l] + j) * LDP + ar[l]] = hb;
                Al[(ac[l] + j) * LDP + ar[l]] = f2tf32(aa[j] - __uint_as_float(hb));
            }
            *(uint4*)&Bh[br[l] * LDP + bc[l]] = pbh[l];
            *(uint4*)&Bl[br[l] * LDP + bc[l]] = pbl[l];
        }
    };

    fetch(0);
    store();
    __syncthreads();

    for (int t = 0; t < nt_tiles; t++) {
        if (t + 1 < nt_tiles) fetch(t + 1);
#pragma unroll
        for (int ks = 0; ks < 2; ks++) {
            int k0 = ks * 8;
            uint32_t ahf[2][4], alf[2][4];
#pragma unroll
            for (int mt = 0; mt < 2; mt++) {
                int m0 = wm + mt * 16;
                ahf[mt][0] = Ah[(k0 + tg) * LDP + m0 + g];
                ahf[mt][1] = Ah[(k0 + tg) * LDP + m0 + g + 8];
                ahf[mt][2] = Ah[(k0 + tg + 4) * LDP + m0 + g];
                ahf[mt][3] = Ah[(k0 + tg + 4) * LDP + m0 + g + 8];
                alf[mt][0] = Al[(k0 + tg) * LDP + m0 + g];
                alf[mt][1] = Al[(k0 + tg) * LDP + m0 + g + 8];
                alf[mt][2] = Al[(k0 + tg + 4) * LDP + m0 + g];
                alf[mt][3] = Al[(k0 + tg + 4) * LDP + m0 + g + 8];
            }
#pragma unroll
            for (int nt = 0; nt < 8; nt++) {
                int n0 = wn + nt * 8;
                uint32_t b0h = Bh[(k0 + tg) * LDP + n0 + g];
                uint32_t b1h = Bh[(k0 + tg + 4) * LDP + n0 + g];
                uint32_t b0l = Bl[(k0 + tg) * LDP + n0 + g];
                uint32_t b1l = Bl[(k0 + tg + 4) * LDP + n0 + g];
#pragma unroll
                for (int mt = 0; mt < 2; mt++) {
                    mma_tf32(acc[mt][nt], ahf[mt], b0h, b1h);
                    mma_tf32(acc[mt][nt], alf[mt], b0h, b1h);
                    mma_tf32(acc[mt][nt], ahf[mt], b0l, b1l);
                }
            }
        }
        if (t + 1 < nt_tiles) {
            __syncthreads();
            store();
            __syncthreads();
        }
    }

#pragma unroll
    for (int mt = 0; mt < 2; mt++) {
        int r0 = brow + wm + mt * 16 + g;
        int r1 = r0 + 8;
#pragma unroll
        for (int nt = 0; nt < 8; nt++) {
            int col = wn + nt * 8 + tg * 2;
            float b0 = bias[col], b1 = bias[col + 1];
            if (r0 < NN)
                *(__half2*)&catH[(size_t)r0 * NCAT + col] =
                    __floats2half2_rn(acc[mt][nt][0] + b0, acc[mt][nt][1] + b1);
            if (r1 < NN)
                *(__half2*)&catH[(size_t)r1 * NCAT + col] =
                    __floats2half2_rn(acc[mt][nt][2] + b0, acc[mt][nt][3] + b1);
        }
    }
}

// ---------------- chain GEMM: fp16 A (exact in tf32), 2-pass ----------------
// hout16[M,128] = A16[M,128] @ B ; messages output (dense stride 64 half2)
__global__ __launch_bounds__(256) void k_mma_h(
    const __half* __restrict__ A, int lda,
    const uint32_t* __restrict__ Bh_g, const uint32_t* __restrict__ Bl_g,
    __half2* __restrict__ hout)
{
    __shared__ uint32_t Ah[BK * LDP];
    __shared__ uint32_t Bh[BK * LDP], Bl[BK * LDP];

    const int tid  = threadIdx.x;
    const int wid  = tid >> 5;
    const int lane = tid & 31;
    const int g    = lane >> 2;
    const int tg   = lane & 3;
    const int wm   = (wid & 3) * 32;
    const int wn   = (wid >> 2) * 64;
    const int brow = blockIdx.x * 128;

    // A tile 128x16 halfs: 1 uint4 (8 halfs) per thread
    const int ar = tid >> 1;
    const int ac = (tid & 1) * 8;
    int br[2], bc[2];
#pragma unroll
    for (int l = 0; l < 2; l++) {
        int v = tid + l * 256;
        br[l] = v >> 5;  bc[l] = (v & 31) * 4;
    }

    float acc[2][8][4];
#pragma unroll
    for (int mt = 0; mt < 2; mt++)
#pragma unroll
        for (int nt = 0; nt < 8; nt++)
#pragma unroll
            for (int j = 0; j < 4; j++) acc[mt][nt][j] = 0.0f;

    const int nt_tiles = HH / BK;   // 8

    uint4 pa, pbh[2], pbl[2];

    auto fetch = [&](int t) {
        int grow = brow + ar;
        pa = make_uint4(0, 0, 0, 0);
        if (grow < NN)
            pa = *(const uint4*)&A[(size_t)grow * lda + t * BK + ac];
#pragma unroll
        for (int l = 0; l < 2; l++) {
            pbh[l] = *(const uint4*)&Bh_g[(size_t)(t * BK + br[l]) * 128 + bc[l]];
            pbl[l] = *(const uint4*)&Bl_g[(size_t)(t * BK + br[l]) * 128 + bc[l]];
        }
    };
    auto store = [&]() {
        const __half2* hp = (const __half2*)&pa;
#pragma unroll
        for (int j = 0; j < 4; j++) {
            float2 f = __half22float2(hp[j]);
            Ah[(ac + 2 * j + 0) * LDP + ar] = f2tf32(f.x);   // exact: fp16 c tf32
            Ah[(ac + 2 * j + 1) * LDP + ar] = f2tf32(f.y);
        }
#pragma unroll
        for (int l = 0; l < 2; l++) {
            *(uint4*)&Bh[br[l] * LDP + bc[l]] = pbh[l];
            *(uint4*)&Bl[br[l] * LDP + bc[l]] = pbl[l];
        }
    };

    fetch(0);
    store();
    __syncthreads();

    for (int t = 0; t < nt_tiles; t++) {
        if (t + 1 < nt_tiles) fetch(t + 1);
#pragma unroll
        for (int ks = 0; ks < 2; ks++) {
            int k0 = ks * 8;
            uint32_t ahf[2][4];
#pragma unroll
            for (int mt = 0; mt < 2; mt++) {
                int m0 = wm + mt * 16;
                ahf[mt][0] = Ah[(k0 + tg) * LDP + m0 + g];
                ahf[mt][1] = Ah[(k0 + tg) * LDP + m0 + g + 8];
                ahf[mt][2] = Ah[(k0 + tg + 4) * LDP + m0 + g];
                ahf[mt][3] = Ah[(k0 + tg + 4) * LDP + m0 + g + 8];
            }
#pragma unroll
            for (int nt = 0; nt < 8; nt++) {
                int n0 = wn + nt * 8;
                uint32_t b0h = Bh[(k0 + tg) * LDP + n0 + g];
                uint32_t b1h = Bh[(k0 + tg + 4) * LDP + n0 + g];
                uint32_t b0l = Bl[(k0 + tg) * LDP + n0 + g];
                uint32_t b1l = Bl[(k0 + tg + 4) * LDP + n0 + g];
#pragma unroll
                for (int mt = 0; mt < 2; mt++) {
                    mma_tf32(acc[mt][nt], ahf[mt], b0h, b1h);   // Ah*Bh
                    mma_tf32(acc[mt][nt], ahf[mt], b0l, b1l);   // Ah*Bl
                }
            }
        }
        if (t + 1 < nt_tiles) {
            __syncthreads();
            store();
            __syncthreads();
        }
    }

#pragma unroll
    for (int mt = 0; mt < 2; mt++) {
        int r0 = brow + wm + mt * 16 + g;
        int r1 = r0 + 8;
#pragma unroll
        for (int nt = 0; nt < 8; nt++) {
            int col = wn + nt * 8 + tg * 2;
            if (r0 < NN)
                hout[(size_t)r0 * 64 + (col >> 1)] =
                    __floats2half2_rn(acc[mt][nt][0], acc[mt][nt][1]);
            if (r1 < NN)
                hout[(size_t)r1 * 64 + (col >> 1)] =
                    __floats2half2_rn(acc[mt][nt][2], acc[mt][nt][3]);
        }
    }
}

// ---------------- CSR aggregation (fp16 in, fp32 accum, fp16 out) -----------
__global__ __launch_bounds__(256) void k_aggr(
    const int* __restrict__ rowptr, const int* __restrict__ csrc,
    const float* __restrict__ cw, const __half2* __restrict__ hwh,
    const float* __restrict__ deg, const float* __restrict__ bias,
    __half* __restrict__ out, int ldo)
{
    int node = (blockIdx.x * blockDim.x + threadIdx.x) >> 5;
    if (node >= NN) return;
    int lane = threadIdx.x & 31;

    const uint2* mh = (const uint2*)hwh;

    auto loadf4 = [&](int n) -> float4 {
        uint2 p = __ldg(&mh[(size_t)n * 32 + lane]);
        __half2 h0 = *(__half2*)&p.x;
        __half2 h1 = *(__half2*)&p.y;
        float2 f0 = __half22float2(h0);
        float2 f1 = __half22float2(h1);
        return make_float4(f0.x, f0.y, f1.x, f1.y);
    };

    float sn = 1.0f / deg[node];
    float4 self = loadf4(node);
    float4 bb = ((const float4*)bias)[lane];
    float4 acc;
    acc.x = self.x * sn + bb.x;
    acc.y = self.y * sn + bb.y;
    acc.z = self.z * sn + bb.z;
    acc.w = self.w * sn + bb.w;

    int e  = rowptr[node];
    int e1 = rowptr[node + 1];
    for (; e + 3 < e1; e += 4) {
        int   s0 = __ldg(&csrc[e]),     s1 = __ldg(&csrc[e + 1]);
        int   s2 = __ldg(&csrc[e + 2]), s3 = __ldg(&csrc[e + 3]);
        float w0 = __ldg(&cw[e]),       w1 = __ldg(&cw[e + 1]);
        float w2 = __ldg(&cw[e + 2]),   w3 = __ldg(&cw[e + 3]);
        float4 v0 = loadf4(s0), v1 = loadf4(s1), v2 = loadf4(s2), v3 = loadf4(s3);
        acc.x += w0 * v0.x + w1 * v1.x + w2 * v2.x + w3 * v3.x;
        acc.y += w0 * v0.y + w1 * v1.y + w2 * v2.y + w3 * v3.y;
        acc.z += w0 * v0.z + w1 * v1.z + w2 * v2.z + w3 * v3.z;
        acc.w += w0 * v0.w + w1 * v1.w + w2 * v2.w + w3 * v3.w;
    }
    for (; e < e1; e++) {
        int   s0 = __ldg(&csrc[e]);
        float w0 = __ldg(&cw[e]);
        float4 v0 = loadf4(s0);
        acc.x += w0 * v0.x;
        acc.y += w0 * v0.y;
        acc.z += w0 * v0.z;
        acc.w += w0 * v0.w;
    }

    union { uint2 u; __half2 h[2]; } pk;
    pk.h[0] = __floats2half2_rn(acc.x, acc.y);
    pk.h[1] = __floats2half2_rn(acc.z, acc.w);
    *(uint2*)&out[(size_t)node * ldo + lane * 4] = pk.u;
}

// ---------------- final: out = cat16 @ W_out + b_out (2-pass TF32) ----------
#define LDO 264   // 264 mod 32 == 8

__global__ __launch_bounds__(256) void k_out(
    const __half* __restrict__ cat,
    const uint32_t* __restrict__ Woh, const uint32_t* __restrict__ Wol,
    const float* __restrict__ b, float* __restrict__ out)
{
    __shared__ uint32_t Ah[BK * LDO];
    __shared__ uint32_t Bh[BK * 40], Bl[BK * 40];

    const int tid  = threadIdx.x;
    const int wid  = tid >> 5;
    const int lane = tid & 31;
    const int g    = lane >> 2;
    const int tg   = lane & 3;
    const int wm   = wid * 32;
    const int brow = blockIdx.x * 256;

    float acc[2][5][4];
#pragma unroll
    for (int mt = 0; mt < 2; mt++)
#pragma unroll
        for (int nt = 0; nt < 5; nt++)
#pragma unroll
            for (int j = 0; j < 4; j++) acc[mt][nt][j] = 0.0f;

    for (int kc = 0; kc < NCAT; kc += BK) {
        // A tile 256x16 halfs: 512 uint4 loads, 2 per thread
#pragma unroll
        for (int l = 0; l < 2; l++) {
            int v  = tid + l * 256;
            int r  = v >> 1;
            int c8 = (v & 1) * 8;
            int grow = brow + r;
            uint4 av = make_uint4(0, 0, 0, 0);
            if (grow < NN)
                av = *(const uint4*)&cat[(size_t)grow * NCAT + kc + c8];
            const __half2* hp = (const __half2*)&av;
#pragma unroll
            for (int j = 0; j < 4; j++) {
                float2 f = __half22float2(hp[j]);
                Ah[(c8 + 2 * j + 0) * LDO + r] = f2tf32(f.x);
                Ah[(c8 + 2 * j + 1) * LDO + r] = f2tf32(f.y);
            }
        }
        for (int idx = tid; idx < BK * 40; idx += 256) {
            Bh[idx] = Woh[kc * 40 + idx];
            Bl[idx] = Wol[kc * 40 + idx];
        }
        __syncthreads();

#pragma unroll
        for (int ks = 0; ks < 2; ks++) {
            int k0 = ks * 8;
            uint32_t ahf[2][4];
#pragma unroll
            for (int mt = 0; mt < 2; mt++) {
                int m0 = wm + mt * 16;
                ahf[mt][0] = Ah[(k0 + tg) * LDO + m0 + g];
                ahf[mt][1] = Ah[(k0 + tg) * LDO + m0 + g + 8];
                ahf[mt][2] = Ah[(k0 + tg + 4) * LDO + m0 + g];
                ahf[mt][3] = Ah[(k0 + tg + 4) * LDO + m0 + g + 8];
            }
#pragma unroll
            for (int nt = 0; nt < 5; nt++) {
                int n0 = nt * 8;
                uint32_t b0h = Bh[(k0 + tg) * 40 + n0 + g];
                uint32_t b1h = Bh[(k0 + tg + 4) * 40 + n0 + g];
                uint32_t b0l = Bl[(k0 + tg) * 40 + n0 + g];
                uint32_t b1l = Bl[(k0 + tg + 4) * 40 + n0 + g];
#pragma unroll
                for (int mt = 0; mt < 2; mt++) {
                    mma_tf32(acc[mt][nt], ahf[mt], b0h, b1h);
                    mma_tf32(acc[mt][nt], ahf[mt], b0l, b1l);
                }
            }
        }
        __syncthreads();
    }

#pragma unroll
    for (int mt = 0; mt < 2; mt++) {
        int r0 = brow + wm + mt * 16 + g;
        int r1 = r0 + 8;
#pragma unroll
        for (int nt = 0; nt < 5; nt++) {
            int col = nt * 8 + tg * 2;
            float b0 = b[col], b1 = b[col + 1];
            if (r0 < NN) {
                float2 v = make_float2(acc[mt][nt][0] + b0, acc[mt][nt][1] + b1);
                *(float2*)&out[(size_t)r0 * CC + col] = v;
            }
            if (r1 < NN) {
                float2 v = make_float2(acc[mt][nt][2] + b0, acc[mt][nt][3] + b1);
                *(float2*)&out[(size_t)r1 * CC + col] = v;
            }
        }
    }
}

// ---------------- launch (single stream) -------------------------------------
extern "C" void kernel_launch(void* const* d_in, const int* in_sizes, int n_in,
                              void* d_out, int out_size) {
    const float* x     = (const float*)d_in[0];
    const int*   ei    = (const int*)  d_in[1];
    const float* ew    = (const float*)d_in[2];
    const float* W_in  = (const float*)d_in[3];
    const float* b_in  = (const float*)d_in[4];
    const float* W_gcn = (const float*)d_in[5];
    const float* b_gcn = (const float*)d_in[6];
    const float* W_out = (const float*)d_in[7];
    const float* b_out = (const float*)d_in[8];
    float* out = (float*)d_out;

    float *deg, *cw;
    __half *t0, *t1, *cat;
    __half2* hwh;
    uint32_t *bh, *bl, *woh, *wol;
    int *cnt, *rowptr, *cursor, *csrc, *bsum, *boff;
    cudaGetSymbolAddress((void**)&deg,    g_deg);
    cudaGetSymbolAddress((void**)&hwh,    g_hwh);
    cudaGetSymbolAddress((void**)&t0,     g_t0);
    cudaGetSymbolAddress((void**)&t1,     g_t1);
    cudaGetSymbolAddress((void**)&cat,    g_cat);
    cudaGetSymbolAddress((void**)&bh,     g_bh);
    cudaGetSymbolAddress((void**)&bl,     g_bl);
    cudaGetSymbolAddress((void**)&woh,    g_woh);
    cudaGetSymbolAddress((void**)&wol,    g_wol);
    cudaGetSymbolAddress((void**)&cnt,    g_cnt);
    cudaGetSymbolAddress((void**)&rowptr, g_rowptr);
    cudaGetSymbolAddress((void**)&cursor, g_cursor);
    cudaGetSymbolAddress((void**)&csrc,   g_csrc);
    cudaGetSymbolAddress((void**)&cw,     g_cw);
    cudaGetSymbolAddress((void**)&bsum,   g_bsum);
    cudaGetSymbolAddress((void**)&boff,   g_boff);

    const int gb = (NN + 127) / 128;

    // launches 0..4, then the input GEMM at index 5 (ncu -s 5 profiles it)
    k_wsplit  <<<(WMAIN + WOUTN + 255) / 256, 256>>>(W_in, W_gcn, W_out,
                                                     bh, bl, woh, wol);
    k_deg_init<<<(NN + 255) / 256, 256>>>(deg, cnt);
    k_deg_acc <<<(EE + 255) / 256, 256>>>(ei, ew, deg, cnt);
    k_scan1   <<<NB_SCAN, 256>>>(cnt, bsum);
    k_scan2   <<<1, 256>>>(bsum, boff, rowptr);
    k_mma_in  <<<gb, 256>>>(x, bh, bl, b_in, cat);        // h -> cat[:,0:128]
    k_scan3   <<<NB_SCAN, 256>>>(cnt, boff, rowptr, cursor);
    k_fill    <<<(EE + 255) / 256, 256>>>(ei, ew, deg, cursor, csrc, cw);

    // one GCN conv: hwh = fp16(in @ Wk); dst = aggr + self + bias (fp16)
    auto gcn = [&](const __half* in, int lda, int k, __half* dst, int ldo) {
        k_mma_h<<<gb, 256>>>(in, lda, bh + FF * HH + (size_t)k * HH * HH,
                             bl + FF * HH + (size_t)k * HH * HH, hwh);
        k_aggr <<<(NN * 32 + 255) / 256, 256>>>(rowptr, csrc, cw, hwh, deg,
                                                b_gcn + (size_t)k * HH, dst, ldo);
    };

    const __half* h = cat;                      // stride NCAT

    gcn(h,  NCAT, 0, cat + 1 * HH, NCAT);       // chain 1

    gcn(h,  NCAT, 1, t0, HH);                   // chain 2
    gcn(t0, HH,   2, cat + 2 * HH, NCAT);

    gcn(h,  NCAT, 3, t0, HH);                   // chain 3
    gcn(t0, HH,   4, t1, HH);
    gcn(t1, HH,   5, cat + 3 * HH, NCAT);

    gcn(h,  NCAT, 6, t0, HH);                   // chain 4
    gcn(t0, HH,   7, t1, HH);
    gcn(t1, HH,   8, t0, HH);
    gcn(t0, HH,   9, cat + 4 * HH, NCAT);

    // out = cat @ W_out + b_out
    k_out<<<(NN + 255) / 256, 256>>>(cat, woh, wol, b_out, out);
}

// round 9
// speedup vs baseline: 2.1095x; 1.3652x over previous
#include <cuda_runtime.h>
#include <cuda_fp16.h>
#include <cstdint>

#define NN 50000
#define EE 800000
#define FF 512
#define HH 128
#define CC 40
#define NCAT 640     // (1 + 4) * 128
#define NB_SCAN 196  // ceil(NN / 256)

// pair counts (k-pair packed half2 weights)
#define PIN   (256 * 128)     // input weights:  512x128 -> 256x128 pairs
#define PCH   (64 * 128)      // one chain layer: 128x128 -> 64x128 pairs
#define PMAIN (PIN + 10 * PCH)
#define POUT  (320 * 40)      // out weights: 640x40 -> 320x40 pairs

// ---------------- scratch (device globals; no allocation allowed) -----------
static __device__ __align__(256) float    g_deg[NN];
static __device__ __align__(256) __half2  g_hwh[NN * 64];      // fp16 messages
static __device__ __align__(256) __half   g_t0[NN * HH];       // fp16 chain temps
static __device__ __align__(256) __half   g_t1[NN * HH];
static __device__ __align__(256) __half   g_cat[(size_t)NN * NCAT];  // fp16 concat
// pre-packed split-fp16 weights: [k2][n] = half2(W[2k2][n], W[2k2+1][n])
static __device__ __align__(256) uint32_t g_wph[PMAIN], g_wpl[PMAIN];
static __device__ __align__(256) uint32_t g_woh[POUT],  g_wol[POUT];
// CSR scratch
static __device__ __align__(256) int   g_cnt[NN];
static __device__ __align__(256) int   g_rowptr[NN + 1];
static __device__ __align__(256) int   g_cursor[NN];
static __device__ __align__(256) int   g_csrc[EE];
static __device__ __align__(256) float g_cw[EE];
static __device__ __align__(256) int   g_bsum[256];
static __device__ __align__(256) int   g_boff[256];

__device__ __forceinline__ uint32_t pack2(float a, float b) {
    __half2 h = __floats2half2_rn(a, b);
    return *(uint32_t*)&h;
}

__device__ __forceinline__ void mma_f16(float c[4], uint32_t a0, uint32_t a1,
                                        uint32_t a2, uint32_t a3,
                                        uint32_t b0, uint32_t b1) {
    asm volatile(
        "mma.sync.aligned.m16n8k16.row.col.f32.f16.f16.f32 "
        "{%0,%1,%2,%3}, {%4,%5,%6,%7}, {%8,%9}, {%0,%1,%2,%3};"
        : "+f"(c[0]), "+f"(c[1]), "+f"(c[2]), "+f"(c[3])
        : "r"(a0), "r"(a1), "r"(a2), "r"(a3), "r"(b0), "r"(b1));
}

// ---------------- weight pre-split + k-pair pack ----------------------------
// hi = fp16(w), lo = fp16(w - hi); packed as half2 over (2k2, 2k2+1).
__global__ void k_wsplit(const float* __restrict__ W_in,
                         const float* __restrict__ W_gcn,
                         const float* __restrict__ W_out,
                         uint32_t* __restrict__ wph, uint32_t* __restrict__ wpl,
                         uint32_t* __restrict__ woh, uint32_t* __restrict__ wol) {
    int i = blockIdx.x * blockDim.x + threadIdx.x;
    float v0, v1;
    uint32_t *ph, *pl;
    int idx;
    if (i < PIN) {                      // input: [512][128]
        int k2 = i / 128, n = i % 128;
        v0 = W_in[(2 * k2) * 128 + n];
        v1 = W_in[(2 * k2 + 1) * 128 + n];
        ph = wph; pl = wpl; idx = i;
    } else if (i < PMAIN) {             // chains: 10 x [128][128]
        int j = i - PIN;
        int l = j / PCH, r = j % PCH;
        int k2 = r / 128, n = r % 128;
        v0 = W_gcn[l * HH * HH + (2 * k2) * 128 + n];
        v1 = W_gcn[l * HH * HH + (2 * k2 + 1) * 128 + n];
        ph = wph; pl = wpl; idx = i;
    } else if (i < PMAIN + POUT) {      // out: [640][40]
        int j = i - PMAIN;
        int k2 = j / 40, n = j % 40;
        v0 = W_out[(2 * k2) * 40 + n];
        v1 = W_out[(2 * k2 + 1) * 40 + n];
        ph = woh; pl = wol; idx = j;
    } else return;

    __half h0 = __float2half_rn(v0), h1 = __float2half_rn(v1);
    float l0 = v0 - __half2float(h0), l1 = v1 - __half2float(h1);
    __half2 hh = __halves2half2(h0, h1);
    ph[idx] = *(uint32_t*)&hh;
    pl[idx] = pack2(l0, l1);
}

// ---------------- degree / CSR build ----------------------------------------
__global__ void k_deg_init(float* __restrict__ deg, int* __restrict__ cnt) {
    int i = blockIdx.x * blockDim.x + threadIdx.x;
    if (i < NN) { deg[i] = 1.0f; cnt[i] = 0; }
}

__global__ void k_deg_acc(const int* __restrict__ ei, const float* __restrict__ ew,
                          float* __restrict__ deg, int* __restrict__ cnt) {
    int e = blockIdx.x * blockDim.x + threadIdx.x;
    if (e < EE) {
        int d = ei[EE + e];
        atomicAdd(&deg[d], ew[e]);
        atomicAdd(&cnt[d], 1);
    }
}

__global__ void k_scan1(const int* __restrict__ cnt, int* __restrict__ bsum) {
    __shared__ int s[256];
    int i = blockIdx.x * 256 + threadIdx.x;
    s[threadIdx.x] = (i < NN) ? cnt[i] : 0;
    __syncthreads();
    for (int off = 128; off > 0; off >>= 1) {
        if (threadIdx.x < off) s[threadIdx.x] += s[threadIdx.x + off];
        __syncthreads();
    }
    if (threadIdx.x == 0) bsum[blockIdx.x] = s[0];
}

__global__ void k_scan2(const int* __restrict__ bsum, int* __restrict__ boff,
                        int* __restrict__ rowptr) {
    __shared__ int s[256];
    int t = threadIdx.x;
    int v = (t < NB_SCAN) ? bsum[t] : 0;
    s[t] = v;
    __syncthreads();
    for (int off = 1; off < 256; off <<= 1) {
        int u = (t >= off) ? s[t - off] : 0;
        __syncthreads();
        s[t] += u;
        __syncthreads();
    }
    boff[t] = s[t] - v;
    if (t == 255) rowptr[NN] = s[255];
}

__global__ void k_scan3(const int* __restrict__ cnt, const int* __restrict__ boff,
                        int* __restrict__ rowptr, int* __restrict__ cursor) {
    __shared__ int s[256];
    int i = blockIdx.x * 256 + threadIdx.x;
    int t = threadIdx.x;
    int v = (i < NN) ? cnt[i] : 0;
    s[t] = v;
    __syncthreads();
    for (int off = 1; off < 256; off <<= 1) {
        int u = (t >= off) ? s[t - off] : 0;
        __syncthreads();
        s[t] += u;
        __syncthreads();
    }
    int ex = boff[blockIdx.x] + s[t] - v;
    if (i < NN) { rowptr[i] = ex; cursor[i] = ex; }
}

__global__ void k_fill(const int* __restrict__ ei, const float* __restrict__ ew,
                       const float* __restrict__ deg, int* __restrict__ cursor,
                       int* __restrict__ csrc, float* __restrict__ cw) {
    int e = blockIdx.x * blockDim.x + threadIdx.x;
    if (e < EE) {
        int s = ei[e], d = ei[EE + e];
        int pos = atomicAdd(&cursor[d], 1);
        csrc[pos] = s;
        cw[pos]   = ew[e] * rsqrtf(deg[s]) * rsqrtf(deg[d]);
    }
}

#define LDP 136   // stride (u32) : bank = 8*tg + g -> all 32 lanes distinct

// ---------------- input GEMM: fp32 A split to fp16 hi/lo, 3-pass HMMA -------
// cat16[:,0:128] = x[M,512] @ W_in + b_in ; block 128x128, 8 warps 4x2.
__global__ __launch_bounds__(256) void k_mma_in(
    const float* __restrict__ A,
    const uint32_t* __restrict__ Bh_g, const uint32_t* __restrict__ Bl_g,
    const float* __restrict__ bias, __half* __restrict__ catH)
{
    __shared__ uint32_t Ah[8 * LDP], Al[8 * LDP];   // [k2][m] half2
    __shared__ uint32_t Bh[8 * LDP], Bl[8 * LDP];   // [k2][n] half2

    const int tid  = threadIdx.x;
    const int wid  = tid >> 5;
    const int lane = tid & 31;
    const int g    = lane >> 2;
    const int tg   = lane & 3;
    const int wm   = (wid & 3) * 32;
    const int wn   = (wid >> 2) * 64;
    const int brow = blockIdx.x * 128;

    // A: 128x16 fp32 = 512 float4, 2/thread ; B: 8x128 u32 = 256 uint4, 1/thread
    int ar[2], ac[2];
#pragma unroll
    for (int l = 0; l < 2; l++) {
        int v = tid + l * 256;
        ar[l] = v >> 2;  ac[l] = (v & 3) * 4;
    }
    const int brr = tid >> 5;          // 0..7
    const int bcc = (tid & 31) * 4;    // 0..124

    float acc[2][8][4];
#pragma unroll
    for (int mt = 0; mt < 2; mt++)
#pragma unroll
        for (int nt = 0; nt < 8; nt++)
#pragma unroll
            for (int j = 0; j < 4; j++) acc[mt][nt][j] = 0.0f;

    const int nt_tiles = FF / 16;      // 32

    float4 pa[2];
    uint4  pbh, pbl;

    auto fetch = [&](int t) {
#pragma unroll
        for (int l = 0; l < 2; l++) {
            int grow = brow + ar[l];
            pa[l] = make_float4(0.f, 0.f, 0.f, 0.f);
            if (grow < NN)
                pa[l] = *(const float4*)&A[(size_t)grow * FF + t * 16 + ac[l]];
        }
        pbh = *(const uint4*)&Bh_g[(size_t)(t * 8 + brr) * 128 + bcc];
        pbl = *(const uint4*)&Bl_g[(size_t)(t * 8 + brr) * 128 + bcc];
    };
    auto store = [&]() {
#pragma unroll
        for (int l = 0; l < 2; l++) {
            float fx = pa[l].x, fy = pa[l].y, fz = pa[l].z, fw = pa[l].w;
            __half hx = __float2half_rn(fx), hy = __float2half_rn(fy);
            __half hz = __float2half_rn(fz), hw_ = __float2half_rn(fw);
            __half2 h01 = __halves2half2(hx, hy), h23 = __halves2half2(hz, hw_);
            int k2 = ac[l] >> 1;       // pair index base
            Ah[(k2 + 0) * LDP + ar[l]] = *(uint32_t*)&h01;
            Ah[(k2 + 1) * LDP + ar[l]] = *(uint32_t*)&h23;
            Al[(k2 + 0) * LDP + ar[l]] =
                pack2(fx - __half2float(hx), fy - __half2float(hy));
            Al[(k2 + 1) * LDP + ar[l]] =
                pack2(fz - __half2float(hz), fw - __half2float(hw_));
        }
        *(uint4*)&Bh[brr * LDP + bcc] = pbh;
        *(uint4*)&Bl[brr * LDP + bcc] = pbl;
    };

    fetch(0);
    store();
    __syncthreads();

    for (int t = 0; t < nt_tiles; t++) {
        if (t + 1 < nt_tiles) fetch(t + 1);

        uint32_t a0h[2], a1h[2], a2h[2], a3h[2];
        uint32_t a0l[2], a1l[2], a2l[2], a3l[2];
#pragma unroll
        for (int mt = 0; mt < 2; mt++) {
            int m0 = wm + mt * 16;
            a0h[mt] = Ah[tg * LDP + m0 + g];
            a1h[mt] = Ah[tg * LDP + m0 + g + 8];
            a2h[mt] = Ah[(tg + 4) * LDP + m0 + g];
            a3h[mt] = Ah[(tg + 4) * LDP + m0 + g + 8];
            a0l[mt] = Al[tg * LDP + m0 + g];
            a1l[mt] = Al[tg * LDP + m0 + g + 8];
            a2l[mt] = Al[(tg + 4) * LDP + m0 + g];
            a3l[mt] = Al[(tg + 4) * LDP + m0 + g + 8];
        }
#pragma unroll
        for (int nt = 0; nt < 8; nt++) {
            int n0 = wn + nt * 8;
            uint32_t b0h = Bh[tg * LDP + n0 + g];
            uint32_t b1h = Bh[(tg + 4) * LDP + n0 + g];
            uint32_t b0l = Bl[tg * LDP + n0 + g];
            uint32_t b1l = Bl[(tg + 4) * LDP + n0 + g];
#pragma unroll
            for (int mt = 0; mt < 2; mt++) {
                mma_f16(acc[mt][nt], a0h[mt], a1h[mt], a2h[mt], a3h[mt], b0h, b1h);
                mma_f16(acc[mt][nt], a0l[mt], a1l[mt], a2l[mt], a3l[mt], b0h, b1h);
                mma_f16(acc[mt][nt], a0h[mt], a1h[mt], a2h[mt], a3h[mt], b0l, b1l);
            }
        }
        if (t + 1 < nt_tiles) {
            __syncthreads();
            store();
            __syncthreads();
        }
    }

#pragma unroll
    for (int mt = 0; mt < 2; mt++) {
        int r0 = brow + wm + mt * 16 + g;
        int r1 = r0 + 8;
#pragma unroll
        for (int nt = 0; nt < 8; nt++) {
            int col = wn + nt * 8 + tg * 2;
            float b0 = bias[col], b1 = bias[col + 1];
            if (r0 < NN)
                *(__half2*)&catH[(size_t)r0 * NCAT + col] =
                    __floats2half2_rn(acc[mt][nt][0] + b0, acc[mt][nt][1] + b1);
            if (r1 < NN)
                *(__half2*)&catH[(size_t)r1 * NCAT + col] =
                    __floats2half2_rn(acc[mt][nt][2] + b0, acc[mt][nt][3] + b1);
        }
    }
}

// ---------------- chain GEMM: fp16 A (exact), 2-pass HMMA -------------------
// hout16[M,128] = A16[M,128(lda)] @ Wk ; messages output (stride 64 half2)
__global__ __launch_bounds__(256) void k_mma_h(
    const __half* __restrict__ A, int lda,
    const uint32_t* __restrict__ Bh_g, const uint32_t* __restrict__ Bl_g,
    __half2* __restrict__ hout)
{
    __shared__ uint32_t As[8 * LDP];                // [k2][m] half2 (exact)
    __shared__ uint32_t Bh[8 * LDP], Bl[8 * LDP];

    const int tid  = threadIdx.x;
    const int wid  = tid >> 5;
    const int lane = tid & 31;
    const int g    = lane >> 2;
    const int tg   = lane & 3;
    const int wm   = (wid & 3) * 32;
    const int wn   = (wid >> 2) * 64;
    const int brow = blockIdx.x * 128;

    // A: 128x16 fp16 = 256 uint4, 1/thread ; B: 256 uint4, 1/thread each
    const int ar  = tid >> 1;
    const int ak2 = (tid & 1) * 4;     // pair-index base (cols 0-7 or 8-15)
    const int brr = tid >> 5;
    const int bcc = (tid & 31) * 4;

    float acc[2][8][4];
#pragma unroll
    for (int mt = 0; mt < 2; mt++)
#pragma unroll
        for (int nt = 0; nt < 8; nt++)
#pragma unroll
            for (int j = 0; j < 4; j++) acc[mt][nt][j] = 0.0f;

    const int nt_tiles = HH / 16;      // 8

    uint4 pa, pbh, pbl;

    auto fetch = [&](int t) {
        int grow = brow + ar;
        pa = make_uint4(0, 0, 0, 0);
        if (grow < NN)
            pa = *(const uint4*)&A[(size_t)grow * lda + t * 16 + ak2 * 2];
        pbh = *(const uint4*)&Bh_g[(size_t)(t * 8 + brr) * 128 + bcc];
        pbl = *(const uint4*)&Bl_g[(size_t)(t * 8 + brr) * 128 + bcc];
    };
    auto store = [&]() {
        const uint32_t* hp = (const uint32_t*)&pa;   // 4 half2 pairs, already paired
#pragma unroll
        for (int j = 0; j < 4; j++)
            As[(ak2 + j) * LDP + ar] = hp[j];
        *(uint4*)&Bh[brr * LDP + bcc] = pbh;
        *(uint4*)&Bl[brr * LDP + bcc] = pbl;
    };

    fetch(0);
    store();
    __syncthreads();

    for (int t = 0; t < nt_tiles; t++) {
        if (t + 1 < nt_tiles) fetch(t + 1);

        uint32_t a0[2], a1[2], a2[2], a3[2];
#pragma unroll
        for (int mt = 0; mt < 2; mt++) {
            int m0 = wm + mt * 16;
            a0[mt] = As[tg * LDP + m0 + g];
            a1[mt] = As[tg * LDP + m0 + g + 8];
            a2[mt] = As[(tg + 4) * LDP + m0 + g];
            a3[mt] = As[(tg + 4) * LDP + m0 + g + 8];
        }
#pragma unroll
        for (int nt = 0; nt < 8; nt++) {
            int n0 = wn + nt * 8;
            uint32_t b0h = Bh[tg * LDP + n0 + g];
            uint32_t b1h = Bh[(tg + 4) * LDP + n0 + g];
            uint32_t b0l = Bl[tg * LDP + n0 + g];
            uint32_t b1l = Bl[(tg + 4) * LDP + n0 + g];
#pragma unroll
            for (int mt = 0; mt < 2; mt++) {
                mma_f16(acc[mt][nt], a0[mt], a1[mt], a2[mt], a3[mt], b0h, b1h);
                mma_f16(acc[mt][nt], a0[mt], a1[mt], a2[mt], a3[mt], b0l, b1l);
            }
        }
        if (t + 1 < nt_tiles) {
            __syncthreads();
            store();
            __syncthreads();
        }
    }

#pragma unroll
    for (int mt = 0; mt < 2; mt++) {
        int r0 = brow + wm + mt * 16 + g;
        int r1 = r0 + 8;
#pragma unroll
        for (int nt = 0; nt < 8; nt++) {
            int col = wn + nt * 8 + tg * 2;
            if (r0 < NN)
                hout[(size_t)r0 * 64 + (col >> 1)] =
                    __floats2half2_rn(acc[mt][nt][0], acc[mt][nt][1]);
            if (r1 < NN)
                hout[(size_t)r1 * 64 + (col >> 1)] =
                    __floats2half2_rn(acc[mt][nt][2], acc[mt][nt][3]);
        }
    }
}

// ---------------- CSR aggregation (fp16 in, fp32 accum, fp16 out) -----------
__global__ __launch_bounds__(256) void k_aggr(
    const int* __restrict__ rowptr, const int* __restrict__ csrc,
    const float* __restrict__ cw, const __half2* __restrict__ hwh,
    const float* __restrict__ deg, const float* __restrict__ bias,
    __half* __restrict__ out, int ldo)
{
    int node = (blockIdx.x * blockDim.x + threadIdx.x) >> 5;
    if (node >= NN) return;
    int lane = threadIdx.x & 31;

    const uint2* mh = (const uint2*)hwh;

    auto loadf4 = [&](int n) -> float4 {
        uint2 p = __ldg(&mh[(size_t)n * 32 + lane]);
        __half2 h0 = *(__half2*)&p.x;
        __half2 h1 = *(__half2*)&p.y;
        float2 f0 = __half22float2(h0);
        float2 f1 = __half22float2(h1);
        return make_float4(f0.x, f0.y, f1.x, f1.y);
    };

    float sn = 1.0f / deg[node];
    float4 self = loadf4(node);
    float4 bb = ((const float4*)bias)[lane];
    float4 acc;
    acc.x = self.x * sn + bb.x;
    acc.y = self.y * sn + bb.y;
    acc.z = self.z * sn + bb.z;
    acc.w = self.w * sn + bb.w;

    int e  = rowptr[node];
    int e1 = rowptr[node + 1];
    for (; e + 3 < e1; e += 4) {
        int   s0 = __ldg(&csrc[e]),     s1 = __ldg(&csrc[e + 1]);
        int   s2 = __ldg(&csrc[e + 2]), s3 = __ldg(&csrc[e + 3]);
        float w0 = __ldg(&cw[e]),       w1 = __ldg(&cw[e + 1]);
        float w2 = __ldg(&cw[e + 2]),   w3 = __ldg(&cw[e + 3]);
        float4 v0 = loadf4(s0), v1 = loadf4(s1), v2 = loadf4(s2), v3 = loadf4(s3);
        acc.x += w0 * v0.x + w1 * v1.x + w2 * v2.x + w3 * v3.x;
        acc.y += w0 * v0.y + w1 * v1.y + w2 * v2.y + w3 * v3.y;
        acc.z += w0 * v0.z + w1 * v1.z + w2 * v2.z + w3 * v3.z;
        acc.w += w0 * v0.w + w1 * v1.w + w2 * v2.w + w3 * v3.w;
    }
    for (; e < e1; e++) {
        int   s0 = __ldg(&csrc[e]);
        float w0 = __ldg(&cw[e]);
        float4 v0 = loadf4(s0);
        acc.x += w0 * v0.x;
        acc.y += w0 * v0.y;
        acc.z += w0 * v0.z;
        acc.w += w0 * v0.w;
    }

    union { uint2 u; __half2 h[2]; } pk;
    pk.h[0] = __floats2half2_rn(acc.x, acc.y);
    pk.h[1] = __floats2half2_rn(acc.z, acc.w);
    *(uint2*)&out[(size_t)node * ldo + lane * 4] = pk.u;
}

// ---------------- final: out = cat16 @ W_out + b_out (2-pass HMMA) ----------
#define LDA2 264   // 264 mod 32 == 8 -> conflict-free

__global__ __launch_bounds__(256) void k_out(
    const __half* __restrict__ cat,
    const uint32_t* __restrict__ Woh, const uint32_t* __restrict__ Wol,
    const float* __restrict__ b, float* __restrict__ out)
{
    __shared__ uint32_t As[8 * LDA2];               // [k2][m] half2 (256 rows)
    __shared__ uint32_t Bh[8 * 40], Bl[8 * 40];     // [k2][n] ; 40 % 32 == 8

    const int tid  = threadIdx.x;
    const int wid  = tid >> 5;
    const int lane = tid & 31;
    const int g    = lane >> 2;
    const int tg   = lane & 3;
    const int wm   = wid * 32;
    const int brow = blockIdx.x * 256;

    float acc[2][5][4];
#pragma unroll
    for (int mt = 0; mt < 2; mt++)
#pragma unroll
        for (int nt = 0; nt < 5; nt++)
#pragma unroll
            for (int j = 0; j < 4; j++) acc[mt][nt][j] = 0.0f;

    for (int t = 0; t < NCAT / 16; t++) {           // 40 tiles
        // A tile 256x16 halfs = 512 uint4, 2/thread
#pragma unroll
        for (int l = 0; l < 2; l++) {
            int v   = tid + l * 256;
            int r   = v >> 1;
            int k2  = (v & 1) * 4;
            int grow = brow + r;
            uint4 av = make_uint4(0, 0, 0, 0);
            if (grow < NN)
                av = *(const uint4*)&cat[(size_t)grow * NCAT + t * 16 + k2 * 2];
            const uint32_t* hp = (const uint32_t*)&av;
#pragma unroll
            for (int j = 0; j < 4; j++)
                As[(k2 + j) * LDA2 + r] = hp[j];
        }
        // B tile 8x40 u32 = 320
        for (int idx = tid; idx < 8 * 40; idx += 256) {
            Bh[idx] = Woh[t * 320 + idx];
            Bl[idx] = Wol[t * 320 + idx];
        }
        __syncthreads();

        uint32_t a0[2], a1[2], a2[2], a3[2];
#pragma unroll
        for (int mt = 0; mt < 2; mt++) {
            int m0 = wm + mt * 16;
            a0[mt] = As[tg * LDA2 + m0 + g];
            a1[mt] = As[tg * LDA2 + m0 + g + 8];
            a2[mt] = As[(tg + 4) * LDA2 + m0 + g];
            a3[mt] = As[(tg + 4) * LDA2 + m0 + g + 8];
        }
#pragma unroll
        for (int nt = 0; nt < 5; nt++) {
            int n0 = nt * 8;
            uint32_t b0h = Bh[tg * 40 + n0 + g];
            uint32_t b1h = Bh[(tg + 4) * 40 + n0 + g];
            uint32_t b0l = Bl[tg * 40 + n0 + g];
            uint32_t b1l = Bl[(tg + 4) * 40 + n0 + g];
#pragma unroll
            for (int mt = 0; mt < 2; mt++) {
                mma_f16(acc[mt][nt], a0[mt], a1[mt], a2[mt], a3[mt], b0h, b1h);
                mma_f16(acc[mt][nt], a0[mt], a1[mt], a2[mt], a3[mt], b0l, b1l);
            }
        }
        __syncthreads();
    }

#pragma unroll
    for (int mt = 0; mt < 2; mt++) {
        int r0 = brow + wm + mt * 16 + g;
        int r1 = r0 + 8;
#pragma unroll
        for (int nt = 0; nt < 5; nt++) {
            int col = nt * 8 + tg * 2;
            float b0 = b[col], b1 = b[col + 1];
            if (r0 < NN) {
                float2 v = make_float2(acc[mt][nt][0] + b0, acc[mt][nt][1] + b1);
                *(float2*)&out[(size_t)r0 * CC + col] = v;
            }
            if (r1 < NN) {
                float2 v = make_float2(acc[mt][nt][2] + b0, acc[mt][nt][3] + b1);
                *(float2*)&out[(size_t)r1 * CC + col] = v;
            }
        }
    }
}

// ---------------- launch (single stream) -------------------------------------
extern "C" void kernel_launch(void* const* d_in, const int* in_sizes, int n_in,
                              void* d_out, int out_size) {
    const float* x     = (const float*)d_in[0];
    const int*   ei    = (const int*)  d_in[1];
    const float* ew    = (const float*)d_in[2];
    const float* W_in  = (const float*)d_in[3];
    const float* b_in  = (const float*)d_in[4];
    const float* W_gcn = (const float*)d_in[5];
    const float* b_gcn = (const float*)d_in[6];
    const float* W_out = (const float*)d_in[7];
    const float* b_out = (const float*)d_in[8];
    float* out = (float*)d_out;

    float *deg, *cw;
    __half *t0, *t1, *cat;
    __half2* hwh;
    uint32_t *wph, *wpl, *woh, *wol;
    int *cnt, *rowptr, *cursor, *csrc, *bsum, *boff;
    cudaGetSymbolAddress((void**)&deg,    g_deg);
    cudaGetSymbolAddress((void**)&hwh,    g_hwh);
    cudaGetSymbolAddress((void**)&t0,     g_t0);
    cudaGetSymbolAddress((void**)&t1,     g_t1);
    cudaGetSymbolAddress((void**)&cat,    g_cat);
    cudaGetSymbolAddress((void**)&wph,    g_wph);
    cudaGetSymbolAddress((void**)&wpl,    g_wpl);
    cudaGetSymbolAddress((void**)&woh,    g_woh);
    cudaGetSymbolAddress((void**)&wol,    g_wol);
    cudaGetSymbolAddress((void**)&cnt,    g_cnt);
    cudaGetSymbolAddress((void**)&rowptr, g_rowptr);
    cudaGetSymbolAddress((void**)&cursor, g_cursor);
    cudaGetSymbolAddress((void**)&csrc,   g_csrc);
    cudaGetSymbolAddress((void**)&cw,     g_cw);
    cudaGetSymbolAddress((void**)&bsum,   g_bsum);
    cudaGetSymbolAddress((void**)&boff,   g_boff);

    const int gb = (NN + 127) / 128;

    k_wsplit  <<<(PMAIN + POUT + 255) / 256, 256>>>(W_in, W_gcn, W_out,
                                                    wph, wpl, woh, wol);
    k_deg_init<<<(NN + 255) / 256, 256>>>(deg, cnt);
    k_deg_acc <<<(EE + 255) / 256, 256>>>(ei, ew, deg, cnt);
    k_scan1   <<<NB_SCAN, 256>>>(cnt, bsum);
    k_scan2   <<<1, 256>>>(bsum, boff, rowptr);
    k_mma_in  <<<gb, 256>>>(x, wph, wpl, b_in, cat);      // h -> cat[:,0:128]
    k_scan3   <<<NB_SCAN, 256>>>(cnt, boff, rowptr, cursor);
    k_fill    <<<(EE + 255) / 256, 256>>>(ei, ew, deg, cursor, csrc, cw);

    // one GCN conv: hwh = fp16(in @ Wk); dst = aggr + self + bias (fp16)
    auto gcn = [&](const __half* in, int lda, int k, __half* dst, int ldo) {
        k_mma_h<<<gb, 256>>>(in, lda, wph + PIN + (size_t)k * PCH,
                             wpl + PIN + (size_t)k * PCH, hwh);
        k_aggr <<<(NN * 32 + 255) / 256, 256>>>(rowptr, csrc, cw, hwh, deg,
                                                b_gcn + (size_t)k * HH, dst, ldo);
    };

    const __half* h = cat;                      // stride NCAT

    gcn(h,  NCAT, 0, cat + 1 * HH, NCAT);       // chain 1

    gcn(h,  NCAT, 1, t0, HH);                   // chain 2
    gcn(t0, HH,   2, cat + 2 * HH, NCAT);

    gcn(h,  NCAT, 3, t0, HH);                   // chain 3
    gcn(t0, HH,   4, t1, HH);
    gcn(t1, HH,   5, cat + 3 * HH, NCAT);

    gcn(h,  NCAT, 6, t0, HH);                   // chain 4
    gcn(t0, HH,   7, t1, HH);
    gcn(t1, HH,   8, t0, HH);
    gcn(t0, HH,   9, cat + 4 * HH, NCAT);

    // out = cat @ W_out + b_out
    k_out<<<(NN + 255) / 256, 256>>>(cat, woh, wol, b_out, out);
}

// round 10
// speedup vs baseline: 2.2743x; 1.0781x over previous
#include <cuda_runtime.h>
#include <cuda_fp16.h>
#include <cstdint>

#define NN 50000
#define EE 800000
#define FF 512
#define HH 128
#define CC 40
#define NCAT 640     // (1 + 4) * 128
#define NB_SCAN 196  // ceil(NN / 256)

// pair counts (k-pair packed half2 weights)
#define PIN   (256 * 128)     // input weights:  512x128 -> 256x128 pairs
#define PCH   (64 * 128)      // one chain layer: 128x128 -> 64x128 pairs
#define PMAIN (PIN + 10 * PCH)
#define POUT  (320 * 40)      // out weights: 640x40 -> 320x40 pairs

// ---------------- scratch (device globals; no allocation allowed) -----------
static __device__ __align__(256) float    g_deg[NN];
static __device__ __align__(256) __half   g_ah[NN * HH];   // aggregated features
static __device__ __align__(256) __half   g_b1[NN * HH];   // chain buffers
static __device__ __align__(256) __half   g_b2[NN * HH];
static __device__ __align__(256) __half   g_b3[NN * HH];
static __device__ __align__(256) __half   g_cat[(size_t)NN * NCAT];  // fp16 concat
// pre-packed split-fp16 weights: [k2][n] = half2(W[2k2][n], W[2k2+1][n])
static __device__ __align__(256) uint32_t g_wph[PMAIN], g_wpl[PMAIN];
static __device__ __align__(256) uint32_t g_woh[POUT],  g_wol[POUT];
// CSR scratch
static __device__ __align__(256) int   g_cnt[NN];
static __device__ __align__(256) int   g_rowptr[NN + 1];
static __device__ __align__(256) int   g_cursor[NN];
static __device__ __align__(256) int   g_csrc[EE];
static __device__ __align__(256) float g_cw[EE];
static __device__ __align__(256) int   g_bsum[256];
static __device__ __align__(256) int   g_boff[256];

__device__ __forceinline__ uint32_t pack2(float a, float b) {
    __half2 h = __floats2half2_rn(a, b);
    return *(uint32_t*)&h;
}

__device__ __forceinline__ void mma_f16(float c[4], uint32_t a0, uint32_t a1,
                                        uint32_t a2, uint32_t a3,
                                        uint32_t b0, uint32_t b1) {
    asm volatile(
        "mma.sync.aligned.m16n8k16.row.col.f32.f16.f16.f32 "
        "{%0,%1,%2,%3}, {%4,%5,%6,%7}, {%8,%9}, {%0,%1,%2,%3};"
        : "+f"(c[0]), "+f"(c[1]), "+f"(c[2]), "+f"(c[3])
        : "r"(a0), "r"(a1), "r"(a2), "r"(a3), "r"(b0), "r"(b1));
}

// ---------------- weight pre-split + k-pair pack ----------------------------
__global__ void k_wsplit(const float* __restrict__ W_in,
                         const float* __restrict__ W_gcn,
                         const float* __restrict__ W_out,
                         uint32_t* __restrict__ wph, uint32_t* __restrict__ wpl,
                         uint32_t* __restrict__ woh, uint32_t* __restrict__ wol) {
    int i = blockIdx.x * blockDim.x + threadIdx.x;
    float v0, v1;
    uint32_t *ph, *pl;
    int idx;
    if (i < PIN) {                      // input: [512][128]
        int k2 = i / 128, n = i % 128;
        v0 = W_in[(2 * k2) * 128 + n];
        v1 = W_in[(2 * k2 + 1) * 128 + n];
        ph = wph; pl = wpl; idx = i;
    } else if (i < PMAIN) {             // chains: 10 x [128][128]
        int j = i - PIN;
        int l = j / PCH, r = j % PCH;
        int k2 = r / 128, n = r % 128;
        v0 = W_gcn[l * HH * HH + (2 * k2) * 128 + n];
        v1 = W_gcn[l * HH * HH + (2 * k2 + 1) * 128 + n];
        ph = wph; pl = wpl; idx = i;
    } else if (i < PMAIN + POUT) {      // out: [640][40]
        int j = i - PMAIN;
        int k2 = j / 40, n = j % 40;
        v0 = W_out[(2 * k2) * 40 + n];
        v1 = W_out[(2 * k2 + 1) * 40 + n];
        ph = woh; pl = wol; idx = j;
    } else return;

    __half h0 = __float2half_rn(v0), h1 = __float2half_rn(v1);
    float l0 = v0 - __half2float(h0), l1 = v1 - __half2float(h1);
    __half2 hh = __halves2half2(h0, h1);
    ph[idx] = *(uint32_t*)&hh;
    pl[idx] = pack2(l0, l1);
}

// ---------------- degree / CSR build ----------------------------------------
__global__ void k_deg_init(float* __restrict__ deg, int* __restrict__ cnt) {
    int i = blockIdx.x * blockDim.x + threadIdx.x;
    if (i < NN) { deg[i] = 1.0f; cnt[i] = 0; }
}

__global__ void k_deg_acc(const int* __restrict__ ei, const float* __restrict__ ew,
                          float* __restrict__ deg, int* __restrict__ cnt) {
    int e = blockIdx.x * blockDim.x + threadIdx.x;
    if (e < EE) {
        int d = ei[EE + e];
        atomicAdd(&deg[d], ew[e]);
        atomicAdd(&cnt[d], 1);
    }
}

__global__ void k_scan1(const int* __restrict__ cnt, int* __restrict__ bsum) {
    __shared__ int s[256];
    int i = blockIdx.x * 256 + threadIdx.x;
    s[threadIdx.x] = (i < NN) ? cnt[i] : 0;
    __syncthreads();
    for (int off = 128; off > 0; off >>= 1) {
        if (threadIdx.x < off) s[threadIdx.x] += s[threadIdx.x + off];
        __syncthreads();
    }
    if (threadIdx.x == 0) bsum[blockIdx.x] = s[0];
}

__global__ void k_scan2(const int* __restrict__ bsum, int* __restrict__ boff,
                        int* __restrict__ rowptr) {
    __shared__ int s[256];
    int t = threadIdx.x;
    int v = (t < NB_SCAN) ? bsum[t] : 0;
    s[t] = v;
    __syncthreads();
    for (int off = 1; off < 256; off <<= 1) {
        int u = (t >= off) ? s[t - off] : 0;
        __syncthreads();
        s[t] += u;
        __syncthreads();
    }
    boff[t] = s[t] - v;
    if (t == 255) rowptr[NN] = s[255];
}

__global__ void k_scan3(const int* __restrict__ cnt, const int* __restrict__ boff,
                        int* __restrict__ rowptr, int* __restrict__ cursor) {
    __shared__ int s[256];
    int i = blockIdx.x * 256 + threadIdx.x;
    int t = threadIdx.x;
    int v = (i < NN) ? cnt[i] : 0;
    s[t] = v;
    __syncthreads();
    for (int off = 1; off < 256; off <<= 1) {
        int u = (t >= off) ? s[t - off] : 0;
        __syncthreads();
        s[t] += u;
        __syncthreads();
    }
    int ex = boff[blockIdx.x] + s[t] - v;
    if (i < NN) { rowptr[i] = ex; cursor[i] = ex; }
}

__global__ void k_fill(const int* __restrict__ ei, const float* __restrict__ ew,
                       const float* __restrict__ deg, int* __restrict__ cursor,
                       int* __restrict__ csrc, float* __restrict__ cw) {
    int e = blockIdx.x * blockDim.x + threadIdx.x;
    if (e < EE) {
        int s = ei[e], d = ei[EE + e];
        int pos = atomicAdd(&cursor[d], 1);
        csrc[pos] = s;
        cw[pos]   = ew[e] * rsqrtf(deg[s]) * rsqrtf(deg[d]);
    }
}

#define LDP 136   // stride (u32) : conflict-free fragment loads

// ---------------- input GEMM: fp32 A split to fp16 hi/lo, 3-pass HMMA -------
// cat16[:,0:128] = x[M,512] @ W_in + b_in ; block 128x128, 8 warps 4x2.
__global__ __launch_bounds__(256) void k_mma_in(
    const float* __restrict__ A,
    const uint32_t* __restrict__ Bh_g, const uint32_t* __restrict__ Bl_g,
    const float* __restrict__ bias, __half* __restrict__ catH)
{
    __shared__ uint32_t Ah[8 * LDP], Al[8 * LDP];
    __shared__ uint32_t Bh[8 * LDP], Bl[8 * LDP];

    const int tid  = threadIdx.x;
    const int wid  = tid >> 5;
    const int lane = tid & 31;
    const int g    = lane >> 2;
    const int tg   = lane & 3;
    const int wm   = (wid & 3) * 32;
    const int wn   = (wid >> 2) * 64;
    const int brow = blockIdx.x * 128;

    int ar[2], ac[2];
#pragma unroll
    for (int l = 0; l < 2; l++) {
        int v = tid + l * 256;
        ar[l] = v >> 2;  ac[l] = (v & 3) * 4;
    }
    const int brr = tid >> 5;
    const int bcc = (tid & 31) * 4;

    float acc[2][8][4];
#pragma unroll
    for (int mt = 0; mt < 2; mt++)
#pragma unroll
        for (int nt = 0; nt < 8; nt++)
#pragma unroll
            for (int j = 0; j < 4; j++) acc[mt][nt][j] = 0.0f;

    const int nt_tiles = FF / 16;

    float4 pa[2];
    uint4  pbh, pbl;

    auto fetch = [&](int t) {
#pragma unroll
        for (int l = 0; l < 2; l++) {
            int grow = brow + ar[l];
            pa[l] = make_float4(0.f, 0.f, 0.f, 0.f);
            if (grow < NN)
                pa[l] = *(const float4*)&A[(size_t)grow * FF + t * 16 + ac[l]];
        }
        pbh = *(const uint4*)&Bh_g[(size_t)(t * 8 + brr) * 128 + bcc];
        pbl = *(const uint4*)&Bl_g[(size_t)(t * 8 + brr) * 128 + bcc];
    };
    auto store = [&]() {
#pragma unroll
        for (int l = 0; l < 2; l++) {
            float fx = pa[l].x, fy = pa[l].y, fz = pa[l].z, fw = pa[l].w;
            __half hx = __float2half_rn(fx), hy = __float2half_rn(fy);
            __half hz = __float2half_rn(fz), hw_ = __float2half_rn(fw);
            __half2 h01 = __halves2half2(hx, hy), h23 = __halves2half2(hz, hw_);
            int k2 = ac[l] >> 1;
            Ah[(k2 + 0) * LDP + ar[l]] = *(uint32_t*)&h01;
            Ah[(k2 + 1) * LDP + ar[l]] = *(uint32_t*)&h23;
            Al[(k2 + 0) * LDP + ar[l]] =
                pack2(fx - __half2float(hx), fy - __half2float(hy));
            Al[(k2 + 1) * LDP + ar[l]] =
                pack2(fz - __half2float(hz), fw - __half2float(hw_));
        }
        *(uint4*)&Bh[brr * LDP + bcc] = pbh;
        *(uint4*)&Bl[brr * LDP + bcc] = pbl;
    };

    fetch(0);
    store();
    __syncthreads();

    for (int t = 0; t < nt_tiles; t++) {
        if (t + 1 < nt_tiles) fetch(t + 1);

        uint32_t a0h[2], a1h[2], a2h[2], a3h[2];
        uint32_t a0l[2], a1l[2], a2l[2], a3l[2];
#pragma unroll
        for (int mt = 0; mt < 2; mt++) {
            int m0 = wm + mt * 16;
            a0h[mt] = Ah[tg * LDP + m0 + g];
            a1h[mt] = Ah[tg * LDP + m0 + g + 8];
            a2h[mt] = Ah[(tg + 4) * LDP + m0 + g];
            a3h[mt] = Ah[(tg + 4) * LDP + m0 + g + 8];
            a0l[mt] = Al[tg * LDP + m0 + g];
            a1l[mt] = Al[tg * LDP + m0 + g + 8];
            a2l[mt] = Al[(tg + 4) * LDP + m0 + g];
            a3l[mt] = Al[(tg + 4) * LDP + m0 + g + 8];
        }
#pragma unroll
        for (int nt = 0; nt < 8; nt++) {
            int n0 = wn + nt * 8;
            uint32_t b0h = Bh[tg * LDP + n0 + g];
            uint32_t b1h = Bh[(tg + 4) * LDP + n0 + g];
            uint32_t b0l = Bl[tg * LDP + n0 + g];
            uint32_t b1l = Bl[(tg + 4) * LDP + n0 + g];
#pragma unroll
            for (int mt = 0; mt < 2; mt++) {
                mma_f16(acc[mt][nt], a0h[mt], a1h[mt], a2h[mt], a3h[mt], b0h, b1h);
                mma_f16(acc[mt][nt], a0l[mt], a1l[mt], a2l[mt], a3l[mt], b0h, b1h);
                mma_f16(acc[mt][nt], a0h[mt], a1h[mt], a2h[mt], a3h[mt], b0l, b1l);
            }
        }
        if (t + 1 < nt_tiles) {
            __syncthreads();
            store();
            __syncthreads();
        }
    }

#pragma unroll
    for (int mt = 0; mt < 2; mt++) {
        int r0 = brow + wm + mt * 16 + g;
        int r1 = r0 + 8;
#pragma unroll
        for (int nt = 0; nt < 8; nt++) {
            int col = wn + nt * 8 + tg * 2;
            float b0 = bias[col], b1 = bias[col + 1];
            if (r0 < NN)
                *(__half2*)&catH[(size_t)r0 * NCAT + col] =
                    __floats2half2_rn(acc[mt][nt][0] + b0, acc[mt][nt][1] + b1);
            if (r1 < NN)
                *(__half2*)&catH[(size_t)r1 * NCAT + col] =
                    __floats2half2_rn(acc[mt][nt][2] + b0, acc[mt][nt][3] + b1);
        }
    }
}

// ---------------- chain GEMM: fp16 A (exact), 2-pass HMMA, +bias ------------
// dst16[M,128(ldo)] = A16[M,128(lda)] @ Wk + bias
__global__ __launch_bounds__(256) void k_mma_h(
    const __half* __restrict__ A, int lda,
    const uint32_t* __restrict__ Bh_g, const uint32_t* __restrict__ Bl_g,
    const float* __restrict__ bias, __half* __restrict__ dst, int ldo)
{
    __shared__ uint32_t As[8 * LDP];
    __shared__ uint32_t Bh[8 * LDP], Bl[8 * LDP];

    const int tid  = threadIdx.x;
    const int wid  = tid >> 5;
    const int lane = tid & 31;
    const int g    = lane >> 2;
    const int tg   = lane & 3;
    const int wm   = (wid & 3) * 32;
    const int wn   = (wid >> 2) * 64;
    const int brow = blockIdx.x * 128;

    const int ar  = tid >> 1;
    const int ak2 = (tid & 1) * 4;
    const int brr = tid >> 5;
    const int bcc = (tid & 31) * 4;

    float acc[2][8][4];
#pragma unroll
    for (int mt = 0; mt < 2; mt++)
#pragma unroll
        for (int nt = 0; nt < 8; nt++)
#pragma unroll
            for (int j = 0; j < 4; j++) acc[mt][nt][j] = 0.0f;

    const int nt_tiles = HH / 16;

    uint4 pa, pbh, pbl;

    auto fetch = [&](int t) {
        int grow = brow + ar;
        pa = make_uint4(0, 0, 0, 0);
        if (grow < NN)
            pa = *(const uint4*)&A[(size_t)grow * lda + t * 16 + ak2 * 2];
        pbh = *(const uint4*)&Bh_g[(size_t)(t * 8 + brr) * 128 + bcc];
        pbl = *(const uint4*)&Bl_g[(size_t)(t * 8 + brr) * 128 + bcc];
    };
    auto store = [&]() {
        const uint32_t* hp = (const uint32_t*)&pa;
#pragma unroll
        for (int j = 0; j < 4; j++)
            As[(ak2 + j) * LDP + ar] = hp[j];
        *(uint4*)&Bh[brr * LDP + bcc] = pbh;
        *(uint4*)&Bl[brr * LDP + bcc] = pbl;
    };

    fetch(0);
    store();
    __syncthreads();

    for (int t = 0; t < nt_tiles; t++) {
        if (t + 1 < nt_tiles) fetch(t + 1);

        uint32_t a0[2], a1[2], a2[2], a3[2];
#pragma unroll
        for (int mt = 0; mt < 2; mt++) {
            int m0 = wm + mt * 16;
            a0[mt] = As[tg * LDP + m0 + g];
            a1[mt] = As[tg * LDP + m0 + g + 8];
            a2[mt] = As[(tg + 4) * LDP + m0 + g];
            a3[mt] = As[(tg + 4) * LDP + m0 + g + 8];
        }
#pragma unroll
        for (int nt = 0; nt < 8; nt++) {
            int n0 = wn + nt * 8;
            uint32_t b0h = Bh[tg * LDP + n0 + g];
            uint32_t b1h = Bh[(tg + 4) * LDP + n0 + g];
            uint32_t b0l = Bl[tg * LDP + n0 + g];
            uint32_t b1l = Bl[(tg + 4) * LDP + n0 + g];
#pragma unroll
            for (int mt = 0; mt < 2; mt++) {
                mma_f16(acc[mt][nt], a0[mt], a1[mt], a2[mt], a3[mt], b0h, b1h);
                mma_f16(acc[mt][nt], a0[mt], a1[mt], a2[mt], a3[mt], b0l, b1l);
            }
        }
        if (t + 1 < nt_tiles) {
            __syncthreads();
            store();
            __syncthreads();
        }
    }

#pragma unroll
    for (int mt = 0; mt < 2; mt++) {
        int r0 = brow + wm + mt * 16 + g;
        int r1 = r0 + 8;
#pragma unroll
        for (int nt = 0; nt < 8; nt++) {
            int col = wn + nt * 8 + tg * 2;
            float b0 = bias[col], b1 = bias[col + 1];
            if (r0 < NN)
                *(__half2*)&dst[(size_t)r0 * ldo + col] =
                    __floats2half2_rn(acc[mt][nt][0] + b0, acc[mt][nt][1] + b1);
            if (r1 < NN)
                *(__half2*)&dst[(size_t)r1 * ldo + col] =
                    __floats2half2_rn(acc[mt][nt][2] + b0, acc[mt][nt][3] + b1);
        }
    }
}

// ---------------- CSR aggregation: ah = A_norm * H --------------------------
// ah[d] = sum_e w * H[src] + H[d]/deg ; fp16 in/out, fp32 accum; warp/node.
__global__ __launch_bounds__(256) void k_aggr(
    const int* __restrict__ rowptr, const int* __restrict__ csrc,
    const float* __restrict__ cw, const __half* __restrict__ Hin, int lda,
    const float* __restrict__ deg, __half* __restrict__ out)
{
    int node = (blockIdx.x * blockDim.x + threadIdx.x) >> 5;
    if (node >= NN) return;
    int lane = threadIdx.x & 31;

    const uint2* mh = (const uint2*)Hin;
    const int ld2 = lda >> 2;            // uint2 per row

    auto loadf4 = [&](int n) -> float4 {
        uint2 p = __ldg(&mh[(size_t)n * ld2 + lane]);
        __half2 h0 = *(__half2*)&p.x;
        __half2 h1 = *(__half2*)&p.y;
        float2 f0 = __half22float2(h0);
        float2 f1 = __half22float2(h1);
        return make_float4(f0.x, f0.y, f1.x, f1.y);
    };

    float sn = 1.0f / deg[node];
    float4 self = loadf4(node);
    float4 acc;
    acc.x = self.x * sn;
    acc.y = self.y * sn;
    acc.z = self.z * sn;
    acc.w = self.w * sn;

    int e  = rowptr[node];
    int e1 = rowptr[node + 1];
    for (; e + 3 < e1; e += 4) {
        int   s0 = __ldg(&csrc[e]),     s1 = __ldg(&csrc[e + 1]);
        int   s2 = __ldg(&csrc[e + 2]), s3 = __ldg(&csrc[e + 3]);
        float w0 = __ldg(&cw[e]),       w1 = __ldg(&cw[e + 1]);
        float w2 = __ldg(&cw[e + 2]),   w3 = __ldg(&cw[e + 3]);
        float4 v0 = loadf4(s0), v1 = loadf4(s1), v2 = loadf4(s2), v3 = loadf4(s3);
        acc.x += w0 * v0.x + w1 * v1.x + w2 * v2.x + w3 * v3.x;
        acc.y += w0 * v0.y + w1 * v1.y + w2 * v2.y + w3 * v3.y;
        acc.z += w0 * v0.z + w1 * v1.z + w2 * v2.z + w3 * v3.z;
        acc.w += w0 * v0.w + w1 * v1.w + w2 * v2.w + w3 * v3.w;
    }
    for (; e < e1; e++) {
        int   s0 = __ldg(&csrc[e]);
        float w0 = __ldg(&cw[e]);
        float4 v0 = loadf4(s0);
        acc.x += w0 * v0.x;
        acc.y += w0 * v0.y;
        acc.z += w0 * v0.z;
        acc.w += w0 * v0.w;
    }

    union { uint2 u; __half2 h[2]; } pk;
    pk.h[0] = __floats2half2_rn(acc.x, acc.y);
    pk.h[1] = __floats2half2_rn(acc.z, acc.w);
    *(uint2*)&out[(size_t)node * HH + lane * 4] = pk.u;
}

// ---------------- final: out = cat16 @ W_out + b_out (2-pass HMMA) ----------
#define LDA2 264

__global__ __launch_bounds__(256) void k_out(
    const __half* __restrict__ cat,
    const uint32_t* __restrict__ Woh, const uint32_t* __restrict__ Wol,
    const float* __restrict__ b, float* __restrict__ out)
{
    __shared__ uint32_t As[8 * LDA2];
    __shared__ uint32_t Bh[8 * 40], Bl[8 * 40];

    const int tid  = threadIdx.x;
    const int wid  = tid >> 5;
    const int lane = tid & 31;
    const int g    = lane >> 2;
    const int tg   = lane & 3;
    const int wm   = wid * 32;
    const int brow = blockIdx.x * 256;

    float acc[2][5][4];
#pragma unroll
    for (int mt = 0; mt < 2; mt++)
#pragma unroll
        for (int nt = 0; nt < 5; nt++)
#pragma unroll
            for (int j = 0; j < 4; j++) acc[mt][nt][j] = 0.0f;

    for (int t = 0; t < NCAT / 16; t++) {
#pragma unroll
        for (int l = 0; l < 2; l++) {
            int v   = tid + l * 256;
            int r   = v >> 1;
            int k2  = (v & 1) * 4;
            int grow = brow + r;
            uint4 av = make_uint4(0, 0, 0, 0);
            if (grow < NN)
                av = *(const uint4*)&cat[(size_t)grow * NCAT + t * 16 + k2 * 2];
            const uint32_t* hp = (const uint32_t*)&av;
#pragma unroll
            for (int j = 0; j < 4; j++)
                As[(k2 + j) * LDA2 + r] = hp[j];
        }
        for (int idx = tid; idx < 8 * 40; idx += 256) {
            Bh[idx] = Woh[t * 320 + idx];
            Bl[idx] = Wol[t * 320 + idx];
        }
        __syncthreads();

        uint32_t a0[2], a1[2], a2[2], a3[2];
#pragma unroll
        for (int mt = 0; mt < 2; mt++) {
            int m0 = wm + mt * 16;
            a0[mt] = As[tg * LDA2 + m0 + g];
            a1[mt] = As[tg * LDA2 + m0 + g + 8];
            a2[mt] = As[(tg + 4) * LDA2 + m0 + g];
            a3[mt] = As[(tg + 4) * LDA2 + m0 + g + 8];
        }
#pragma unroll
        for (int nt = 0; nt < 5; nt++) {
            int n0 = nt * 8;
            uint32_t b0h = Bh[tg * 40 + n0 + g];
            uint32_t b1h = Bh[(tg + 4) * 40 + n0 + g];
            uint32_t b0l = Bl[tg * 40 + n0 + g];
            uint32_t b1l = Bl[(tg + 4) * 40 + n0 + g];
#pragma unroll
            for (int mt = 0; mt < 2; mt++) {
                mma_f16(acc[mt][nt], a0[mt], a1[mt], a2[mt], a3[mt], b0h, b1h);
                mma_f16(acc[mt][nt], a0[mt], a1[mt], a2[mt], a3[mt], b0l, b1l);
            }
        }
        __syncthreads();
    }

#pragma unroll
    for (int mt = 0; mt < 2; mt++) {
        int r0 = brow + wm + mt * 16 + g;
        int r1 = r0 + 8;
#pragma unroll
        for (int nt = 0; nt < 5; nt++) {
            int col = nt * 8 + tg * 2;
            float b0 = b[col], b1 = b[col + 1];
            if (r0 < NN) {
                float2 v = make_float2(acc[mt][nt][0] + b0, acc[mt][nt][1] + b1);
                *(float2*)&out[(size_t)r0 * CC + col] = v;
            }
            if (r1 < NN) {
                float2 v = make_float2(acc[mt][nt][2] + b0, acc[mt][nt][3] + b1);
                *(float2*)&out[(size_t)r1 * CC + col] = v;
            }
        }
    }
}

// ---------------- launch (single stream) -------------------------------------
extern "C" void kernel_launch(void* const* d_in, const int* in_sizes, int n_in,
                              void* d_out, int out_size) {
    const float* x     = (const float*)d_in[0];
    const int*   ei    = (const int*)  d_in[1];
    const float* ew    = (const float*)d_in[2];
    const float* W_in  = (const float*)d_in[3];
    const float* b_in  = (const float*)d_in[4];
    const float* W_gcn = (const float*)d_in[5];
    const float* b_gcn = (const float*)d_in[6];
    const float* W_out = (const float*)d_in[7];
    const float* b_out = (const float*)d_in[8];
    float* out = (float*)d_out;

    float *deg, *cw;
    __half *ah, *b1, *b2, *b3, *cat;
    uint32_t *wph, *wpl, *woh, *wol;
    int *cnt, *rowptr, *cursor, *csrc, *bsum, *boff;
    cudaGetSymbolAddress((void**)&deg,    g_deg);
    cudaGetSymbolAddress((void**)&ah,     g_ah);
    cudaGetSymbolAddress((void**)&b1,     g_b1);
    cudaGetSymbolAddress((void**)&b2,     g_b2);
    cudaGetSymbolAddress((void**)&b3,     g_b3);
    cudaGetSymbolAddress((void**)&cat,    g_cat);
    cudaGetSymbolAddress((void**)&wph,    g_wph);
    cudaGetSymbolAddress((void**)&wpl,    g_wpl);
    cudaGetSymbolAddress((void**)&woh,    g_woh);
    cudaGetSymbolAddress((void**)&wol,    g_wol);
    cudaGetSymbolAddress((void**)&cnt,    g_cnt);
    cudaGetSymbolAddress((void**)&rowptr, g_rowptr);
    cudaGetSymbolAddress((void**)&cursor, g_cursor);
    cudaGetSymbolAddress((void**)&csrc,   g_csrc);
    cudaGetSymbolAddress((void**)&cw,     g_cw);
    cudaGetSymbolAddress((void**)&bsum,   g_bsum);
    cudaGetSymbolAddress((void**)&boff,   g_boff);

    const int gb  = (NN + 127) / 128;
    const int ga  = (NN * 32 + 255) / 256;

    k_wsplit  <<<(PMAIN + POUT + 255) / 256, 256>>>(W_in, W_gcn, W_out,
                                                    wph, wpl, woh, wol);
    k_deg_init<<<(NN + 255) / 256, 256>>>(deg, cnt);
    k_deg_acc <<<(EE + 255) / 256, 256>>>(ei, ew, deg, cnt);
    k_scan1   <<<NB_SCAN, 256>>>(cnt, bsum);
    k_scan2   <<<1, 256>>>(bsum, boff, rowptr);
    k_mma_in  <<<gb, 256>>>(x, wph, wpl, b_in, cat);      // h -> cat[:,0:128]
    k_scan3   <<<NB_SCAN, 256>>>(cnt, boff, rowptr, cursor);
    k_fill    <<<(EE + 255) / 256, 256>>>(ei, ew, deg, cursor, csrc, cw);

    auto gemm = [&](const __half* in, int lda, int k, __half* dst, int ldo) {
        k_mma_h<<<gb, 256>>>(in, lda, wph + PIN + (size_t)k * PCH,
                             wpl + PIN + (size_t)k * PCH,
                             b_gcn + (size_t)k * HH, dst, ldo);
    };
    auto aggr = [&](const __half* in, int lda) {
        k_aggr<<<ga, 256>>>(rowptr, csrc, cw, in, lda, deg, ah);
    };

    const __half* h = cat;                       // stride NCAT

    // shared first-layer aggregation: ah = A_norm * h
    aggr(h, NCAT);
    gemm(ah, HH, 0, cat + 1 * HH, NCAT);         // chain 1 done
    gemm(ah, HH, 1, b1, HH);                     // chain 2 L1
    gemm(ah, HH, 3, b2, HH);                     // chain 3 L1
    gemm(ah, HH, 6, b3, HH);                     // chain 4 L1

    // chain 2
    aggr(b1, HH);
    gemm(ah, HH, 2, cat + 2 * HH, NCAT);

    // chain 3
    aggr(b2, HH);
    gemm(ah, HH, 4, b1, HH);
    aggr(b1, HH);
    gemm(ah, HH, 5, cat + 3 * HH, NCAT);

    // chain 4
    aggr(b3, HH);
    gemm(ah, HH, 7, b1, HH);
    aggr(b1, HH);
    gemm(ah, HH, 8, b2, HH);
    aggr(b2, HH);
    gemm(ah, HH, 9, cat + 4 * HH, NCAT);

    // out = cat @ W_out + b_out
    k_out<<<(NN + 255) / 256, 256>>>(cat, woh, wol, b_out, out);
}